// round 10
// baseline (speedup 1.0000x reference)
#include <cuda_runtime.h>
#include <cstdint>

#define Bsz  128
#define Ssz  512
#define Hsz  512

#define NBLK 128     // 1 CTA per SM, all co-resident
#define NTHR 1024    // 32 warps -> 8 per SMSP
#define NSPL 8       // k-splits
#define KS   64      // k-range per split (8 x 64 = 512)

typedef unsigned long long ull;

// Persistent device state (no allocations allowed)
__device__ float    g_Hbuf[2][Hsz][Bsz];   // double-buffered H, [hidden][batch]
__device__ float    g_xT[Ssz][Bsz];        // x transposed to [t][b]
__device__ unsigned g_bar;                 // monotonic grid-barrier counter

// ---------- packed f32x2 helpers ----------
__device__ __forceinline__ ull pack2(float lo, float hi) {
    ull r; asm("mov.b64 %0, {%1, %2};" : "=l"(r) : "f"(lo), "f"(hi)); return r;
}
__device__ __forceinline__ void unpack2(ull v, float& lo, float& hi) {
    asm("mov.b64 {%0, %1}, %2;" : "=f"(lo), "=f"(hi) : "l"(v));
}
__device__ __forceinline__ void ffma2(ull& d, ull a, ull b) {
    asm("fma.rn.f32x2 %0, %1, %2, %0;" : "+l"(d) : "l"(a), "l"(b));
}
__device__ __forceinline__ float sigmoidf_(float v) {
    float e = __expf(-v);
    return __fdividef(1.0f, 1.0f + e);
}
__device__ __forceinline__ float tanhf_(float v) {
    float x = fminf(fmaxf(v, -15.0f), 15.0f);
    float t = __expf(2.0f * x);
    return __fdividef(t - 1.0f, t + 1.0f);
}

// ---------- cp.async helpers ----------
__device__ __forceinline__ void cp16(uint32_t dst_smem, const void* src) {
    asm volatile("cp.async.cg.shared.global [%0], [%1], 16;"
                 :: "r"(dst_smem), "l"(src));
}
__device__ __forceinline__ void cp_commit() {
    asm volatile("cp.async.commit_group;");
}
template<int N> __device__ __forceinline__ void cp_wait() {
    asm volatile("cp.async.wait_group %0;" :: "n"(N));
}

// ---------- grid barrier (R7 proven: release-arrive / acquire-spin) ----------
__device__ __forceinline__ void grid_barrier(unsigned target) {
    __syncthreads();
    if (threadIdx.x == 0) {
        asm volatile("red.release.gpu.global.add.u32 [%0], 1;"
                     :: "l"(&g_bar) : "memory");
        unsigned v;
        do {
            asm volatile("ld.acquire.gpu.global.u32 %0, [%1];"
                         : "=r"(v) : "l"(&g_bar) : "memory");
        } while (v < target);
    }
    __syncthreads();
}

// ---------- init: reset barrier, transpose H_prev and x ----------
__global__ void lstm_init_kernel(const float* __restrict__ Hprev,
                                 const float* __restrict__ x) {
    int i = blockIdx.x * blockDim.x + threadIdx.x;
    if (i == 0) g_bar = 0;
    if (i < Bsz * Hsz) {                       // H_prev [B][H] -> [h][b]
        int b = i / Hsz, h = i % Hsz;
        g_Hbuf[0][h][b] = Hprev[i];
    }
    if (i < Bsz * Ssz) {                       // x [B][S] -> [t][b]
        int t = i >> 7, b = i & 127;
        g_xT[t][b] = x[b * Ssz + t];
    }
}

// ---------- main persistent kernel ----------
__global__ __launch_bounds__(NTHR, 1)
void lstm_kernel(const float* __restrict__ Cprev,
                 const float* __restrict__ Wi, const float* __restrict__ bi,
                 const float* __restrict__ Wf, const float* __restrict__ bf,
                 const float* __restrict__ Wc, const float* __restrict__ bc,
                 const float* __restrict__ Wo, const float* __restrict__ bo,
                 float* __restrict__ out)
{
    extern __shared__ float smem[];
    float* Ws    = smem;                    // [512][32]  weight slice (64KB)
    float* Hs    = Ws + Hsz * 32;           // 32 x [64k][16b] warp-private (128KB)
    float* parts = Hs + Hsz * 64;           // [32 gc][64 b] atomic acc (8KB)
    float* W0s   = parts + 2048;            // [32]
    float* Bs    = W0s + 32;                // [32]

    const int tid  = threadIdx.x;
    const int warp = tid >> 5;
    const int lane = tid & 31;
    const int s    = warp >> 2;             // k-split 0..7
    const int w2   = warp & 3;              // batch quarter 0..3
    const int ty   = lane & 7;              // hidden unit within CTA (0..7)
    const int txw  = lane >> 3;             // batch tile within warp (0..3)
    const int tx   = txw | (w2 << 2);       // batch tile (0..15)

    const int cta   = blockIdx.x;
    const int b_off = (cta & 1) * 64;
    const int h_off = (cta >> 1) * 8;
    const int b0    = b_off + tx * 4;
    const int h     = h_off + ty;
    const int kbeg  = s * KS;

    // --- one-time weight slice load: Ws[k][gc], gc = ty*4 + gate ---
    const float* Wg[4] = {Wi, Wf, Wc, Wo};
    const float* bg[4] = {bi, bf, bc, bo};
    for (int idx = tid; idx < Hsz * 32; idx += NTHR) {
        int k = idx >> 5, gc = idx & 31;
        int hh = h_off + (gc >> 2), g = gc & 3;
        Ws[idx] = Wg[g][(k + 1) * Hsz + hh];
    }
    if (tid < 32) {
        int hh = h_off + (tid >> 2), g = tid & 3;
        W0s[tid] = Wg[g][hh];
        Bs[tid]  = bg[g][hh];
    }
    // zero the atomic partial buffer once
    for (int idx = tid; idx < 2048; idx += NTHR) parts[idx] = 0.0f;

    // warp-private H staging: warp stages exactly the 4KB it consumes
    // region = warp*1024 floats; row r (=k-kbeg) holds its 16 batches
    float* Hwarp = Hs + warp * 1024;
    uint32_t hs_dst = (uint32_t)__cvta_generic_to_shared(
                          Hwarp + (lane >> 2) * 16 + (lane & 3) * 4);
    const char* hsrc_base = (const char*)
        &g_Hbuf[0][kbeg + (lane >> 2)][b_off + w2 * 16 + (lane & 3) * 4];
    const size_t hbuf_stride = (size_t)Hsz * Bsz * sizeof(float);

    // --- C state in registers (only s==7 threads own it) ---
    float Creg[4], Hn[4];
#pragma unroll
    for (int j = 0; j < 4; ++j) Creg[j] = Cprev[(b0 + j) * Hsz + h];

    __syncthreads();   // weights + parts-zero ready

    int cur = 0;
    for (int t = 0; t < Ssz; ++t) {
        // ---- per-warp staging: 4 chunks of 16 k-rows (1KB each) ----
        {
            const char* src = hsrc_base + (size_t)cur * hbuf_stride;
#pragma unroll
            for (int c = 0; c < 4; ++c) {
#pragma unroll
                for (int i = 0; i < 2; ++i) {
                    int ro = c * 16 + i * 8;
                    cp16(hs_dst + ro * 64, src + (size_t)ro * Bsz * 4);
                }
                cp_commit();
            }
        }

        // zero accumulators (identical for all warps; seeding moved to epilogue)
        ull acc[2][4];
#pragma unroll
        for (int g = 0; g < 4; ++g) { acc[0][g] = 0ull; acc[1][g] = 0ull; }

        // ---- GEMM eighth, chunks pipelined against own staging ----
        const float4* Hs4 = (const float4*)Hwarp + txw;           // + kk*4
        const float4* Ws4 = (const float4*)Ws + kbeg * 8 + ty;    // + kk*8
#pragma unroll
        for (int c = 0; c < 4; ++c) {
            if      (c == 0) cp_wait<3>();
            else if (c == 1) cp_wait<2>();
            else if (c == 2) cp_wait<1>();
            else             cp_wait<0>();
            __syncwarp();
#pragma unroll 8
            for (int kk2 = 0; kk2 < 16; ++kk2) {
                int kk = c * 16 + kk2;
                float4 h4 = Hs4[kk * 4];
                float4 w4 = Ws4[kk * 8];
                ull h01 = pack2(h4.x, h4.y);
                ull h23 = pack2(h4.z, h4.w);
                ull wd;
                wd = pack2(w4.x, w4.x); ffma2(acc[0][0], h01, wd); ffma2(acc[1][0], h23, wd);
                wd = pack2(w4.y, w4.y); ffma2(acc[0][1], h01, wd); ffma2(acc[1][1], h23, wd);
                wd = pack2(w4.z, w4.z); ffma2(acc[0][2], h01, wd); ffma2(acc[1][2], h23, wd);
                wd = pack2(w4.w, w4.w); ffma2(acc[0][3], h01, wd); ffma2(acc[1][3], h23, wd);
            }
        }

        // k-split partials: splits 0..6 atomically add into shared buffer
        if (s < NSPL - 1) {
#pragma unroll
            for (int g = 0; g < 4; ++g) {
                float v0, v1, v2, v3;
                unpack2(acc[0][g], v0, v1);
                unpack2(acc[1][g], v2, v3);
                float* p = &parts[(ty * 4 + g) * 64 + tx * 4];
                atomicAdd(p + 0, v0); atomicAdd(p + 1, v1);
                atomicAdd(p + 2, v2); atomicAdd(p + 3, v3);
            }
        }
        // sync the 8 warps (one per split) sharing this batch quarter
        asm volatile("bar.sync %0, 256;" :: "r"(1 + w2) : "memory");

        if (s == NSPL - 1) {
            float4 xa = *(const float4*)&g_xT[t][b0];
#pragma unroll
            for (int g = 0; g < 4; ++g) {
                float* p = &parts[(ty * 4 + g) * 64 + tx * 4];
                float4 ps = *(const float4*)p;
                *(float4*)p = make_float4(0.f, 0.f, 0.f, 0.f);  // re-zero for next step
                float a0, a1, a2, a3;
                unpack2(acc[0][g], a0, a1);
                unpack2(acc[1][g], a2, a3);
                float w0 = W0s[ty * 4 + g], bb = Bs[ty * 4 + g];
                // reuse acc as final pre-activations
                acc[0][g] = pack2(fmaf(xa.x, w0, a0 + ps.x + bb),
                                  fmaf(xa.y, w0, a1 + ps.y + bb));
                acc[1][g] = pack2(fmaf(xa.z, w0, a2 + ps.z + bb),
                                  fmaf(xa.w, w0, a3 + ps.w + bb));
            }
            // gate order: g0=i, g1=f, g2=c, g3=o
            float ip[4], fp[4], cp[4], op[4];
            unpack2(acc[0][0], ip[0], ip[1]); unpack2(acc[1][0], ip[2], ip[3]);
            unpack2(acc[0][1], fp[0], fp[1]); unpack2(acc[1][1], fp[2], fp[3]);
            unpack2(acc[0][2], cp[0], cp[1]); unpack2(acc[1][2], cp[2], cp[3]);
            unpack2(acc[0][3], op[0], op[1]); unpack2(acc[1][3], op[2], op[3]);
#pragma unroll
            for (int j = 0; j < 4; ++j) {
                float I  = sigmoidf_(ip[j]);
                float F  = sigmoidf_(fp[j]);
                float Ch = tanhf_(cp[j]);
                float Cn = F * Creg[j] + I * Ch;
                Creg[j]  = Cn;
                Hn[j]    = op[j] * tanhf_(Cn);   // O has no sigmoid (faithful)
            }
            *(float4*)&g_Hbuf[cur ^ 1][h][b0] = make_float4(Hn[0], Hn[1], Hn[2], Hn[3]);
        }

        grid_barrier((unsigned)(t + 1) * NBLK);
        cur ^= 1;
    }

    // outputs: (H, H, C), each [B][HID]
    if (s == NSPL - 1) {
#pragma unroll
        for (int j = 0; j < 4; ++j) {
            int base = (b0 + j) * Hsz + h;
            out[base]                 = Hn[j];
            out[Bsz * Hsz + base]     = Hn[j];
            out[2 * Bsz * Hsz + base] = Creg[j];
        }
    }
}

extern "C" void kernel_launch(void* const* d_in, const int* in_sizes, int n_in,
                              void* d_out, int out_size) {
    (void)in_sizes; (void)n_in; (void)out_size;
    const float* x  = (const float*)d_in[0];
    const float* Hp = (const float*)d_in[1];
    const float* Cp = (const float*)d_in[2];
    const float* Wi = (const float*)d_in[3];
    const float* bi = (const float*)d_in[4];
    const float* Wf = (const float*)d_in[5];
    const float* bf = (const float*)d_in[6];
    const float* Wc = (const float*)d_in[7];
    const float* bc = (const float*)d_in[8];
    const float* Wo = (const float*)d_in[9];
    const float* bo = (const float*)d_in[10];

    size_t smem_bytes = (size_t)(Hsz * 32 + Hsz * 64 + 2048 + 64) * sizeof(float);
    cudaFuncSetAttribute(lstm_kernel,
                         cudaFuncAttributeMaxDynamicSharedMemorySize,
                         (int)smem_bytes);

    lstm_init_kernel<<<(Bsz * Hsz + 255) / 256, 256>>>(Hp, x);
    lstm_kernel<<<NBLK, NTHR, smem_bytes>>>(Cp, Wi, bi, Wf, bf, Wc, bc,
                                            Wo, bo, (float*)d_out);
}

// round 11
// speedup vs baseline: 1.9177x; 1.9177x over previous
#include <cuda_runtime.h>
#include <cstdint>

#define Bsz  128
#define Ssz  512
#define Hsz  512

#define NBLK 128     // 1 CTA per SM, all co-resident
#define NTHR 512     // 16 warps -> 4 per SMSP
#define NSPL 8       // k-splits (2 warps each)
#define KS   64      // k-range per split

typedef unsigned long long ull;

// Persistent device state (no allocations allowed)
__device__ float    g_Hbuf[2][Hsz][Bsz];   // double-buffered H, [hidden][batch]
__device__ float    g_xT[Ssz][Bsz];        // x transposed to [t][b]
__device__ unsigned g_bar;                 // monotonic grid-barrier counter

// ---------- packed f32x2 helpers ----------
__device__ __forceinline__ ull pack2(float lo, float hi) {
    ull r; asm("mov.b64 %0, {%1, %2};" : "=l"(r) : "f"(lo), "f"(hi)); return r;
}
__device__ __forceinline__ void unpack2(ull v, float& lo, float& hi) {
    asm("mov.b64 {%0, %1}, %2;" : "=f"(lo), "=f"(hi) : "l"(v));
}
__device__ __forceinline__ void ffma2(ull& d, ull a, ull b) {
    asm("fma.rn.f32x2 %0, %1, %2, %0;" : "+l"(d) : "l"(a), "l"(b));
}
__device__ __forceinline__ float sigmoidf_(float v) {
    float e = __expf(-v);
    return __fdividef(1.0f, 1.0f + e);
}
__device__ __forceinline__ float tanhf_(float v) {
    float x = fminf(fmaxf(v, -15.0f), 15.0f);
    float t = __expf(2.0f * x);
    return __fdividef(t - 1.0f, t + 1.0f);
}

// ---------- cp.async helpers ----------
__device__ __forceinline__ void cp16(uint32_t dst_smem, const void* src) {
    asm volatile("cp.async.cg.shared.global [%0], [%1], 16;"
                 :: "r"(dst_smem), "l"(src));
}
__device__ __forceinline__ void cp_commit() {
    asm volatile("cp.async.commit_group;");
}
template<int N> __device__ __forceinline__ void cp_wait() {
    asm volatile("cp.async.wait_group %0;" :: "n"(N));
}

// ---------- grid barrier (R7 proven: release-arrive / acquire-spin) ----------
__device__ __forceinline__ void grid_barrier(unsigned target) {
    __syncthreads();
    if (threadIdx.x == 0) {
        asm volatile("red.release.gpu.global.add.u32 [%0], 1;"
                     :: "l"(&g_bar) : "memory");
        unsigned v;
        do {
            asm volatile("ld.acquire.gpu.global.u32 %0, [%1];"
                         : "=r"(v) : "l"(&g_bar) : "memory");
        } while (v < target);
    }
    __syncthreads();
}

// ---------- init: reset barrier, transpose H_prev and x ----------
__global__ void lstm_init_kernel(const float* __restrict__ Hprev,
                                 const float* __restrict__ x) {
    int i = blockIdx.x * blockDim.x + threadIdx.x;
    if (i == 0) g_bar = 0;
    if (i < Bsz * Hsz) {                       // H_prev [B][H] -> [h][b]
        int b = i / Hsz, h = i % Hsz;
        g_Hbuf[0][h][b] = Hprev[i];
    }
    if (i < Bsz * Ssz) {                       // x [B][S] -> [t][b]
        int t = i >> 7, b = i & 127;
        g_xT[t][b] = x[b * Ssz + t];
    }
}

// ---------- main persistent kernel ----------
__global__ __launch_bounds__(NTHR, 1)
void lstm_kernel(const float* __restrict__ Cprev,
                 const float* __restrict__ Wi, const float* __restrict__ bi,
                 const float* __restrict__ Wf, const float* __restrict__ bf,
                 const float* __restrict__ Wc, const float* __restrict__ bc,
                 const float* __restrict__ Wo, const float* __restrict__ bo,
                 float* __restrict__ out)
{
    extern __shared__ float smem[];
    float* Ws  = smem;                      // [512][32]  weight slice (64KB)
    float* Hs  = Ws + Hsz * 32;             // 16 x [64k][32b] warp-private (128KB)
    float* Cs  = Hs + Hsz * 64;             // [8 h][64 b] C state (2KB)
    float* W0s = Cs + 8 * 64;               // [32]
    float* Bs  = W0s + 32;                  // [32]
    // partials alias the UPPER HALF of Hs (dead after GEMM + sync):
    // parts[s][gc][64b], xor-swizzled within the 64-batch row
    float* parts = Hs + 8 * 2048;           // 8 x 2048 floats = 64KB

    const int tid  = threadIdx.x;
    const int warp = tid >> 5;
    const int lane = tid & 31;
    const int s    = warp >> 1;             // k-split 0..7
    const int half = warp & 1;              // batch half (32 each)
    const int ty   = lane & 7;              // hidden unit (0..7)
    const int txw  = lane >> 3;             // batch octet within half (0..3)

    const int cta   = blockIdx.x;
    const int b_off = (cta & 1) * 64;
    const int h_off = (cta >> 1) * 8;
    const int kbeg  = s * KS;

    // epilogue ownership: one (batch, h) per thread
    const int eb  = tid & 63;               // local batch 0..63
    const int ehl = tid >> 6;               // local h 0..7

    // --- one-time weight slice load: Ws[k][gc], gc = ty*4 + gate ---
    const float* Wg[4] = {Wi, Wf, Wc, Wo};
    const float* bg[4] = {bi, bf, bc, bo};
    for (int idx = tid; idx < Hsz * 32; idx += NTHR) {
        int k = idx >> 5, gc = idx & 31;
        int hh = h_off + (gc >> 2), g = gc & 3;
        Ws[idx] = Wg[g][(k + 1) * Hsz + hh];
    }
    if (tid < 32) {
        int hh = h_off + (tid >> 2), g = tid & 3;
        W0s[tid] = Wg[g][hh];
        Bs[tid]  = bg[g][hh];
    }
    // C state to smem: Cs[hl][b]
    Cs[ehl * 64 + eb] = Cprev[(b_off + eb) * Hsz + h_off + ehl];

    // warp-private H staging: region = warp*2048 floats, row r = 32 batches
    float* Hwarp = Hs + warp * 2048;
    uint32_t hs_dst0 = (uint32_t)__cvta_generic_to_shared(
                           Hwarp + txw * 32 + (lane & 7) * 4);
    const char* hsrc0 = (const char*)
        &g_Hbuf[0][kbeg + txw][b_off + half * 32 + (lane & 7) * 4];
    const size_t hbuf_stride = (size_t)Hsz * Bsz * sizeof(float);

    float HnL = 0.0f, CnL = 0.0f;           // final-step values for output

    __syncthreads();

    int cur = 0;
    for (int t = 0; t < Ssz; ++t) {
        // x for this thread's epilogue (coalesced scalar)
        float xa = g_xT[t][b_off + eb];

        // ---- per-warp staging: 4 chunks of 16 k-rows (2KB each) ----
        {
            const char* src = hsrc0 + (size_t)cur * hbuf_stride;
#pragma unroll
            for (int c = 0; c < 4; ++c) {
#pragma unroll
                for (int i = 0; i < 4; ++i) {
                    int ro = c * 16 + i * 4;         // + txw inside precomputed
                    cp16(hs_dst0 + ro * 128, src + (size_t)ro * Bsz * 4);
                }
                cp_commit();
            }
        }

        // zero accumulators: acc[bp][g], bp = batch pair 0..3 (8 batches)
        ull acc[4][4];
#pragma unroll
        for (int bp = 0; bp < 4; ++bp)
#pragma unroll
            for (int g = 0; g < 4; ++g) acc[bp][g] = 0ull;

        // ---- GEMM eighth: per k, 2 H float4 + 1 W float4, 16 FFMA2 ----
        const float4* Hp4 = (const float4*)Hwarp + txw * 2;   // + k*8
        const float4* Wp4 = (const float4*)Ws + kbeg * 8 + ty; // + kk*8
#pragma unroll
        for (int c = 0; c < 4; ++c) {
            if      (c == 0) cp_wait<3>();
            else if (c == 1) cp_wait<2>();
            else if (c == 2) cp_wait<1>();
            else             cp_wait<0>();
            __syncwarp();
#pragma unroll 8
            for (int kk2 = 0; kk2 < 16; ++kk2) {
                int kk = c * 16 + kk2;
                float4 ha = Hp4[kk * 8];
                float4 hb = Hp4[kk * 8 + 1];
                float4 w4 = Wp4[kk * 8];
                ull h01 = pack2(ha.x, ha.y);
                ull h23 = pack2(ha.z, ha.w);
                ull h45 = pack2(hb.x, hb.y);
                ull h67 = pack2(hb.z, hb.w);
                ull wd;
                wd = pack2(w4.x, w4.x);
                ffma2(acc[0][0], h01, wd); ffma2(acc[1][0], h23, wd);
                ffma2(acc[2][0], h45, wd); ffma2(acc[3][0], h67, wd);
                wd = pack2(w4.y, w4.y);
                ffma2(acc[0][1], h01, wd); ffma2(acc[1][1], h23, wd);
                ffma2(acc[2][1], h45, wd); ffma2(acc[3][1], h67, wd);
                wd = pack2(w4.z, w4.z);
                ffma2(acc[0][2], h01, wd); ffma2(acc[1][2], h23, wd);
                ffma2(acc[2][2], h45, wd); ffma2(acc[3][2], h67, wd);
                wd = pack2(w4.w, w4.w);
                ffma2(acc[0][3], h01, wd); ffma2(acc[1][3], h23, wd);
                ffma2(acc[2][3], h45, wd); ffma2(acc[3][3], h67, wd);
            }
        }

        __syncthreads();   // all GEMM reads done; upper Hs now dead -> parts

        // ---- all splits store partials: parts[s][gc][b^(ty*8)] ----
        {
            const int bseg = half * 32 + txw * 8;     // thread's batch base
#pragma unroll
            for (int g = 0; g < 4; ++g) {
#pragma unroll
                for (int bp2 = 0; bp2 < 2; ++bp2) {
                    float4 v;
                    unpack2(acc[bp2 * 2][g],     v.x, v.y);
                    unpack2(acc[bp2 * 2 + 1][g], v.z, v.w);
                    int xb = (bseg + bp2 * 4) ^ (ty * 8);
                    *(float4*)&parts[s * 2048 + (ty * 4 + g) * 64 + xb] = v;
                }
            }
        }
        __syncthreads();   // partials visible

        // ---- distributed epilogue: each thread owns (eb, ehl) ----
        {
            float gate[4];
#pragma unroll
            for (int g = 0; g < 4; ++g) {
                int gc = ehl * 4 + g;
                int xb = eb ^ (ehl * 8);
                const float* p = &parts[gc * 64 + xb];
                float sum = Bs[gc];
#pragma unroll
                for (int ss = 0; ss < NSPL; ++ss) sum += p[ss * 2048];
                gate[g] = fmaf(xa, W0s[gc], sum);
            }
            float Cold = Cs[ehl * 64 + eb];
            float I  = sigmoidf_(gate[0]);
            float F  = sigmoidf_(gate[1]);
            float Ch = tanhf_(gate[2]);
            float Cn = F * Cold + I * Ch;
            float Hv = gate[3] * tanhf_(Cn);   // O has no sigmoid (faithful)
            Cs[ehl * 64 + eb] = Cn;
            g_Hbuf[cur ^ 1][h_off + ehl][b_off + eb] = Hv;
            HnL = Hv; CnL = Cn;
        }

        grid_barrier((unsigned)(t + 1) * NBLK);
        cur ^= 1;
    }

    // outputs: (H, H, C), each [B][HID]
    {
        int base = (b_off + eb) * Hsz + h_off + ehl;
        out[base]                 = HnL;
        out[Bsz * Hsz + base]     = HnL;
        out[2 * Bsz * Hsz + base] = CnL;
    }
}

extern "C" void kernel_launch(void* const* d_in, const int* in_sizes, int n_in,
                              void* d_out, int out_size) {
    (void)in_sizes; (void)n_in; (void)out_size;
    const float* x  = (const float*)d_in[0];
    const float* Hp = (const float*)d_in[1];
    const float* Cp = (const float*)d_in[2];
    const float* Wi = (const float*)d_in[3];
    const float* bi = (const float*)d_in[4];
    const float* Wf = (const float*)d_in[5];
    const float* bf = (const float*)d_in[6];
    const float* Wc = (const float*)d_in[7];
    const float* bc = (const float*)d_in[8];
    const float* Wo = (const float*)d_in[9];
    const float* bo = (const float*)d_in[10];

    size_t smem_bytes = (size_t)(Hsz * 32 + Hsz * 64 + 8 * 64 + 64) * sizeof(float);
    cudaFuncSetAttribute(lstm_kernel,
                         cudaFuncAttributeMaxDynamicSharedMemorySize,
                         (int)smem_bytes);

    lstm_init_kernel<<<(Bsz * Hsz + 255) / 256, 256>>>(Hp, x);
    lstm_kernel<<<NBLK, NTHR, smem_bytes>>>(Cp, Wi, bi, Wf, bf, Wc, bc,
                                            Wo, bo, (float*)d_out);
}

// round 13
// speedup vs baseline: 2.0071x; 1.0466x over previous
#include <cuda_runtime.h>
#include <cuda_bf16.h>
#include <cstdint>

#define Bsz  128
#define Ssz  512
#define Hsz  512
#define NBLK 128
#define NTHR 512

// smem byte offsets
#define SM_AHI   0         // 64 rows x 1024B  (A hi bf16, chunk-swizzled)
#define SM_ALO   65536     // 64KB
#define SM_BHI   131072    // 32 rows x 1024B  (B hi)
#define SM_BLO   163840    // 32KB
#define SM_PARTS 196608    // 64 x 32 fp32 (8KB), xor-swizzled cols
#define SM_CS    204800    // 64 x 8 fp32 C state (2KB)
#define SM_W0S   206848    // 32 floats
#define SM_BS    206976    // 32 floats
#define SM_TOTAL 207104

// Persistent device state (no allocations allowed)
__device__ float         g_Hbuf[2][Bsz][Hsz];   // [b][h] (A rows contiguous)
__device__ float         g_xT[Ssz][Bsz];
__device__ unsigned      g_bar;
__device__ __nv_bfloat16 g_Whi[2048 * 512];     // [n_glob = h*4+g][k]
__device__ __nv_bfloat16 g_Wlo[2048 * 512];

__device__ __forceinline__ uint32_t smem_u32(const void* p) {
    uint32_t a;
    asm("{ .reg .u64 t; cvta.to.shared.u64 t, %1; cvt.u32.u64 %0, t; }"
        : "=r"(a) : "l"(p));
    return a;
}
__device__ __forceinline__ float sigmoidf_(float v) {
    return __fdividef(1.0f, 1.0f + __expf(-v));
}
__device__ __forceinline__ float tanhf_(float v) {
    float x = fminf(fmaxf(v, -15.0f), 15.0f);
    float t = __expf(2.0f * x);
    return __fdividef(t - 1.0f, t + 1.0f);
}
// pack two fp32 -> bf16x2 (lo_el in low half, hi_el in high half)
__device__ __forceinline__ uint32_t bf2(float hi_el, float lo_el) {
    uint32_t r;
    asm("cvt.rn.bf16x2.f32 %0, %1, %2;" : "=r"(r) : "f"(hi_el), "f"(lo_el));
    return r;
}
__device__ __forceinline__ void ldsm4(uint32_t& r0, uint32_t& r1,
                                      uint32_t& r2, uint32_t& r3, uint32_t a) {
    asm volatile("ldmatrix.sync.aligned.m8n8.x4.shared.b16 {%0,%1,%2,%3}, [%4];"
                 : "=r"(r0), "=r"(r1), "=r"(r2), "=r"(r3) : "r"(a));
}
__device__ __forceinline__ void mma16816(float& c0, float& c1, float& c2, float& c3,
                                         uint32_t a0, uint32_t a1, uint32_t a2, uint32_t a3,
                                         uint32_t b0, uint32_t b1) {
    asm volatile(
        "mma.sync.aligned.m16n8k16.row.col.f32.bf16.bf16.f32 "
        "{%0,%1,%2,%3}, {%4,%5,%6,%7}, {%8,%9}, {%0,%1,%2,%3};"
        : "+f"(c0), "+f"(c1), "+f"(c2), "+f"(c3)
        : "r"(a0), "r"(a1), "r"(a2), "r"(a3), "r"(b0), "r"(b1));
}
__device__ __forceinline__ void sts4(uint32_t addr, uint32_t v0, uint32_t v1,
                                     uint32_t v2, uint32_t v3) {
    asm volatile("st.shared.v4.b32 [%0], {%1,%2,%3,%4};"
                 :: "r"(addr), "r"(v0), "r"(v1), "r"(v2), "r"(v3));
}
__device__ __forceinline__ void grid_barrier(unsigned target) {
    __syncthreads();
    if (threadIdx.x == 0) {
        asm volatile("red.release.gpu.global.add.u32 [%0], 1;"
                     :: "l"(&g_bar) : "memory");
        unsigned v;
        do {
            asm volatile("ld.acquire.gpu.global.u32 %0, [%1];"
                         : "=r"(v) : "l"(&g_bar) : "memory");
        } while (v < target);
    }
    __syncthreads();
}

// ---------- init: barrier, H copy, x transpose, W hi/lo split ----------
__global__ void lstm_init_kernel(const float* __restrict__ Hprev,
                                 const float* __restrict__ x,
                                 const float* __restrict__ Wi,
                                 const float* __restrict__ Wf,
                                 const float* __restrict__ Wc,
                                 const float* __restrict__ Wo) {
    int i = blockIdx.x * blockDim.x + threadIdx.x;
    if (i == 0) g_bar = 0;
    if (i < Bsz * Hsz) g_Hbuf[0][i >> 9][i & 511] = Hprev[i];  // [b][h] direct
    if (i < Bsz * Ssz) {                                        // x -> [t][b]
        int t = i >> 7, b = i & 127;
        g_xT[t][b] = x[b * Ssz + t];
    }
    if (i < 2048 * 512) {
        int n = i >> 9, k = i & 511;
        int h = n >> 2, g = n & 3;
        const float* W = (g == 0) ? Wi : (g == 1) ? Wf : (g == 2) ? Wc : Wo;
        float w = W[(k + 1) * Hsz + h];
        __nv_bfloat16 hi = __float2bfloat16(w);
        float lo = w - __bfloat162float(hi);
        g_Whi[i] = hi;
        g_Wlo[i] = __float2bfloat16(lo);
    }
}

// ---------- main persistent kernel ----------
__global__ __launch_bounds__(NTHR, 1)
void lstm_kernel(const float* __restrict__ Cprev,
                 const float* __restrict__ Wi, const float* __restrict__ bi,
                 const float* __restrict__ Wf, const float* __restrict__ bf,
                 const float* __restrict__ Wc, const float* __restrict__ bc,
                 const float* __restrict__ Wo, const float* __restrict__ bo,
                 float* __restrict__ out)
{
    extern __shared__ char smem[];
    const uint32_t sb = smem_u32(smem);
    float* parts = (float*)(smem + SM_PARTS);
    float* Cs    = (float*)(smem + SM_CS);
    float* W0s   = (float*)(smem + SM_W0S);
    float* Bss   = (float*)(smem + SM_BS);

    const int tid  = threadIdx.x;
    const int warp = tid >> 5;
    const int lane = tid & 31;
    const int cta  = blockIdx.x;
    const int b_off = (cta & 1) * 64;
    const int h_off = (cta >> 1) * 8;

    // W0 / bias
    if (tid < 32) {
        int h = h_off + (tid >> 2), g = tid & 3;
        const float* W = (g == 0) ? Wi : (g == 1) ? Wf : (g == 2) ? Wc : Wo;
        const float* B = (g == 0) ? bi : (g == 1) ? bf : (g == 2) ? bc : bo;
        W0s[tid] = W[h];
        Bss[tid] = B[h];
    }

    // one-time B tiles: 32 rows (gc) x 512 k bf16 hi/lo, chunk-swizzled
    {
        int r  = tid >> 4;                 // gc row 0..31
        int cj = tid & 15;
        int n  = (h_off + (r >> 2)) * 4 + (r & 3);
#pragma unroll
        for (int j = 0; j < 4; ++j) {
            int chunk = cj + 16 * j;       // 16B chunk index (8 bf16)
            uint32_t off = (uint32_t)r * 1024 + (uint32_t)((chunk ^ (r & 7)) << 4);
            uint4 vh = *(const uint4*)&g_Whi[n * 512 + chunk * 8];
            uint4 vl = *(const uint4*)&g_Wlo[n * 512 + chunk * 8];
            sts4(sb + SM_BHI + off, vh.x, vh.y, vh.z, vh.w);
            sts4(sb + SM_BLO + off, vl.x, vl.y, vl.z, vl.w);
        }
    }

    // epilogue/convert mappings
    const int eb  = tid >> 3;              // local batch 0..63 (epilogue + convert)
    const int ehl = tid & 7;               // local h 0..7 (epilogue)
    const int cj8 = tid & 7;               // convert chunk base

    // C state to smem: Cs[b][hl]
    Cs[eb * 8 + ehl] = Cprev[(b_off + eb) * Hsz + h_off + ehl];

    // GEMM warp tile: mt = rows 16mt.., nt = cols 8nt..
    const int mt = warp & 3;
    const int nt = warp >> 2;
    const int arow = mt * 16 + (lane & 7) + ((lane >> 3) & 1) * 8;
    const uint32_t abase = sb + SM_AHI + (uint32_t)arow * 1024;
    const int arx = arow & 7;
    const int ac0 = (lane >> 4) & 1;
    const int brow = nt * 8 + (lane & 7);
    const uint32_t bbase = sb + SM_BHI + (uint32_t)brow * 1024;
    const int brx = brow & 7;
    const int bsel = (lane >> 3) & 3;

    // frag store coords (xor-swizzled parts cols)
    const int fr0 = mt * 16 + (lane >> 2);
    const int fc  = nt * 8 + (lane & 3) * 2;
    const uint32_t fo0 = sb + SM_PARTS + (uint32_t)fr0 * 128
                       + (uint32_t)((fc ^ ((fr0 & 3) << 3)) << 2);

    float HnL[1] = {0.f}, CnL[1] = {0.f};
    float Hn8 = 0.f, Cn8 = 0.f;
    (void)HnL; (void)CnL;

    __syncthreads();

    int cur = 0;
    for (int t = 0; t < Ssz; ++t) {
        // ---- convert H[cur] -> A hi/lo bf16 (chunk-swizzled) ----
        {
            const int row = eb;            // 8 threads per row, 8 chunks each
            const uint32_t rb = (uint32_t)row * 1024;
            const int rx = row & 7;
            const float4* hp = (const float4*)&g_Hbuf[cur][b_off + row][0];
#pragma unroll
            for (int j = 0; j < 8; ++j) {
                int chunk = cj8 + 8 * j;
                float4 va = __ldcg(hp + chunk * 2);
                float4 vb = __ldcg(hp + chunk * 2 + 1);
                uint32_t h0 = bf2(va.y, va.x), h1 = bf2(va.w, va.z);
                uint32_t h2 = bf2(vb.y, vb.x), h3 = bf2(vb.w, vb.z);
                float r0 = __uint_as_float(h0 << 16), r1 = __uint_as_float(h0 & 0xFFFF0000u);
                float r2 = __uint_as_float(h1 << 16), r3 = __uint_as_float(h1 & 0xFFFF0000u);
                float r4 = __uint_as_float(h2 << 16), r5 = __uint_as_float(h2 & 0xFFFF0000u);
                float r6 = __uint_as_float(h3 << 16), r7 = __uint_as_float(h3 & 0xFFFF0000u);
                uint32_t l0 = bf2(va.y - r1, va.x - r0);
                uint32_t l1 = bf2(va.w - r3, va.z - r2);
                uint32_t l2 = bf2(vb.y - r5, vb.x - r4);
                uint32_t l3 = bf2(vb.w - r7, vb.z - r6);
                uint32_t off = rb + (uint32_t)((chunk ^ rx) << 4);
                sts4(sb + SM_AHI + off, h0, h1, h2, h3);
                sts4(sb + SM_ALO + off, l0, l1, l2, l3);
            }
        }
        __syncthreads();

        // ---- GEMM: 16 iterations x 2 k-steps, 3-pass bf16 split ----
        float c0 = 0.f, c1 = 0.f, c2 = 0.f, c3 = 0.f;
#pragma unroll 4
        for (int ks2 = 0; ks2 < 16; ++ks2) {
            uint32_t a0h, a1h, a2h, a3h, a0l, a1l, a2l, a3l;
            uint32_t bh0, bh1, bh2, bh3, bl0, bl1, bl2, bl3;
            uint32_t boff = bbase + (uint32_t)(((ks2 * 4 + bsel) ^ brx) << 4);
            ldsm4(bh0, bh1, bh2, bh3, boff);
            ldsm4(bl0, bl1, bl2, bl3, boff + 32768);
            // even k-step
            uint32_t ao0 = abase + (uint32_t)(((ks2 * 4 + ac0) ^ arx) << 4);
            ldsm4(a0h, a1h, a2h, a3h, ao0);
            ldsm4(a0l, a1l, a2l, a3l, ao0 + 65536);
            mma16816(c0, c1, c2, c3, a0h, a1h, a2h, a3h, bh0, bh1);
            mma16816(c0, c1, c2, c3, a0h, a1h, a2h, a3h, bl0, bl1);
            mma16816(c0, c1, c2, c3, a0l, a1l, a2l, a3l, bh0, bh1);
            // odd k-step
            uint32_t ao1 = abase + (uint32_t)(((ks2 * 4 + 2 + ac0) ^ arx) << 4);
            ldsm4(a0h, a1h, a2h, a3h, ao1);
            ldsm4(a0l, a1l, a2l, a3l, ao1 + 65536);
            mma16816(c0, c1, c2, c3, a0h, a1h, a2h, a3h, bh2, bh3);
            mma16816(c0, c1, c2, c3, a0h, a1h, a2h, a3h, bl2, bl3);
            mma16816(c0, c1, c2, c3, a0l, a1l, a2l, a3l, bh2, bh3);
        }

        // frag -> parts (xor-swizzled)
        asm volatile("st.shared.v2.f32 [%0], {%1,%2};" :: "r"(fo0), "f"(c0), "f"(c1));
        asm volatile("st.shared.v2.f32 [%0], {%1,%2};" :: "r"(fo0 + 8 * 128), "f"(c2), "f"(c3));
        __syncthreads();

        // ---- distributed epilogue: thread owns (eb, ehl) ----
        {
            float xa = g_xT[t][b_off + eb];
            const int sw = (eb & 3) << 3;
            float g0 = parts[eb * 32 + ((ehl * 4 + 0) ^ sw)];
            float g1 = parts[eb * 32 + ((ehl * 4 + 1) ^ sw)];
            float g2 = parts[eb * 32 + ((ehl * 4 + 2) ^ sw)];
            float g3 = parts[eb * 32 + ((ehl * 4 + 3) ^ sw)];
            int gc = ehl * 4;
            float gi = fmaf(xa, W0s[gc + 0], g0 + Bss[gc + 0]);
            float gf = fmaf(xa, W0s[gc + 1], g1 + Bss[gc + 1]);
            float gch = fmaf(xa, W0s[gc + 2], g2 + Bss[gc + 2]);
            float go = fmaf(xa, W0s[gc + 3], g3 + Bss[gc + 3]);
            float Cold = Cs[eb * 8 + ehl];
            float I  = sigmoidf_(gi);
            float F  = sigmoidf_(gf);
            float Ch = tanhf_(gch);
            float Cn = F * Cold + I * Ch;
            float Hv = go * tanhf_(Cn);        // O has no sigmoid (faithful)
            Cs[eb * 8 + ehl] = Cn;
            g_Hbuf[cur ^ 1][b_off + eb][h_off + ehl] = Hv;
            Hn8 = Hv; Cn8 = Cn;
        }

        grid_barrier((unsigned)(t + 1) * NBLK);
        cur ^= 1;
    }

    // outputs: (H, H, C), each [B][HID]
    {
        int base = (b_off + eb) * Hsz + h_off + ehl;
        out[base]                 = Hn8;
        out[Bsz * Hsz + base]     = Hn8;
        out[2 * Bsz * Hsz + base] = Cn8;
    }
}

extern "C" void kernel_launch(void* const* d_in, const int* in_sizes, int n_in,
                              void* d_out, int out_size) {
    (void)in_sizes; (void)n_in; (void)out_size;
    const float* x  = (const float*)d_in[0];
    const float* Hp = (const float*)d_in[1];
    const float* Cp = (const float*)d_in[2];
    const float* Wi = (const float*)d_in[3];
    const float* bi = (const float*)d_in[4];
    const float* Wf = (const float*)d_in[5];
    const float* bf = (const float*)d_in[6];
    const float* Wc = (const float*)d_in[7];
    const float* bc = (const float*)d_in[8];
    const float* Wo = (const float*)d_in[9];
    const float* bo = (const float*)d_in[10];

    cudaFuncSetAttribute(lstm_kernel,
                         cudaFuncAttributeMaxDynamicSharedMemorySize, SM_TOTAL);

    lstm_init_kernel<<<(2048 * 512 + 255) / 256, 256>>>(Hp, x, Wi, Wf, Wc, Wo);
    lstm_kernel<<<NBLK, NTHR, SM_TOTAL>>>(Cp, Wi, bi, Wf, bf, Wc, bc,
                                          Wo, bo, (float*)d_out);
}

// round 14
// speedup vs baseline: 2.4485x; 1.2200x over previous
#include <cuda_runtime.h>
#include <cuda_bf16.h>
#include <cstdint>

#define Bsz  128
#define Ssz  512
#define Hsz  512
#define NBLK 128
#define NTHR 512

// smem byte offsets
#define SM_AHI   0         // 64 rows x 1024B  (A hi bf16, chunk-swizzled)
#define SM_ALO   65536     // 64KB
#define SM_BHI   131072    // 32 rows x 1024B  (B hi)
#define SM_BLO   163840    // 32KB
#define SM_PARTS 196608    // 64 x 32 fp32 (8KB), xor-swizzled cols
#define SM_CS    204800    // 64 x 8 fp32 C state (2KB)
#define SM_W0S   206848    // 32 floats
#define SM_BS    206976    // 32 floats
#define SM_TOTAL 207104

// Persistent device state (no allocations allowed)
__device__ __nv_bfloat16 g_Hhi[2][Bsz][Hsz];    // H split hi, [b][h]
__device__ __nv_bfloat16 g_Hlo[2][Bsz][Hsz];    // H split lo
__device__ float         g_xT[Ssz][Bsz];
__device__ unsigned      g_bar;
__device__ __nv_bfloat16 g_Whi[2048 * 512];     // [n_glob = h*4+g][k]
__device__ __nv_bfloat16 g_Wlo[2048 * 512];

__device__ __forceinline__ uint32_t smem_u32(const void* p) {
    uint32_t a;
    asm("{ .reg .u64 t; cvta.to.shared.u64 t, %1; cvt.u32.u64 %0, t; }"
        : "=r"(a) : "l"(p));
    return a;
}
__device__ __forceinline__ float sigmoidf_(float v) {
    return __fdividef(1.0f, 1.0f + __expf(-v));
}
__device__ __forceinline__ float tanhf_(float v) {
    float x = fminf(fmaxf(v, -15.0f), 15.0f);
    float t = __expf(2.0f * x);
    return __fdividef(t - 1.0f, t + 1.0f);
}
__device__ __forceinline__ void ldsm4(uint32_t& r0, uint32_t& r1,
                                      uint32_t& r2, uint32_t& r3, uint32_t a) {
    asm volatile("ldmatrix.sync.aligned.m8n8.x4.shared.b16 {%0,%1,%2,%3}, [%4];"
                 : "=r"(r0), "=r"(r1), "=r"(r2), "=r"(r3) : "r"(a));
}
__device__ __forceinline__ void mma16816(float& c0, float& c1, float& c2, float& c3,
                                         uint32_t a0, uint32_t a1, uint32_t a2, uint32_t a3,
                                         uint32_t b0, uint32_t b1) {
    asm volatile(
        "mma.sync.aligned.m16n8k16.row.col.f32.bf16.bf16.f32 "
        "{%0,%1,%2,%3}, {%4,%5,%6,%7}, {%8,%9}, {%0,%1,%2,%3};"
        : "+f"(c0), "+f"(c1), "+f"(c2), "+f"(c3)
        : "r"(a0), "r"(a1), "r"(a2), "r"(a3), "r"(b0), "r"(b1));
}
__device__ __forceinline__ void sts4(uint32_t addr, uint32_t v0, uint32_t v1,
                                     uint32_t v2, uint32_t v3) {
    asm volatile("st.shared.v4.b32 [%0], {%1,%2,%3,%4};"
                 :: "r"(addr), "r"(v0), "r"(v1), "r"(v2), "r"(v3));
}
__device__ __forceinline__ void cp16(uint32_t dst_smem, const void* src) {
    asm volatile("cp.async.cg.shared.global [%0], [%1], 16;"
                 :: "r"(dst_smem), "l"(src));
}
__device__ __forceinline__ void cp_commit_wait0() {
    asm volatile("cp.async.commit_group;");
    asm volatile("cp.async.wait_group 0;");
}
__device__ __forceinline__ void grid_barrier(unsigned target) {
    __syncthreads();
    if (threadIdx.x == 0) {
        asm volatile("red.release.gpu.global.add.u32 [%0], 1;"
                     :: "l"(&g_bar) : "memory");
        unsigned v;
        do {
            asm volatile("ld.acquire.gpu.global.u32 %0, [%1];"
                         : "=r"(v) : "l"(&g_bar) : "memory");
        } while (v < target);
    }
    __syncthreads();
}

// ---------- init: barrier, H hi/lo split, x transpose, W hi/lo split ----------
__global__ void lstm_init_kernel(const float* __restrict__ Hprev,
                                 const float* __restrict__ x,
                                 const float* __restrict__ Wi,
                                 const float* __restrict__ Wf,
                                 const float* __restrict__ Wc,
                                 const float* __restrict__ Wo) {
    int i = blockIdx.x * blockDim.x + threadIdx.x;
    if (i == 0) g_bar = 0;
    if (i < Bsz * Hsz) {                       // H_prev [b][h] -> hi/lo bf16
        float v = Hprev[i];
        __nv_bfloat16 hi = __float2bfloat16(v);
        g_Hhi[0][i >> 9][i & 511] = hi;
        g_Hlo[0][i >> 9][i & 511] = __float2bfloat16(v - __bfloat162float(hi));
    }
    if (i < Bsz * Ssz) {                       // x -> [t][b]
        int t = i >> 7, b = i & 127;
        g_xT[t][b] = x[b * Ssz + t];
    }
    if (i < 2048 * 512) {
        int n = i >> 9, k = i & 511;
        int h = n >> 2, g = n & 3;
        const float* W = (g == 0) ? Wi : (g == 1) ? Wf : (g == 2) ? Wc : Wo;
        float w = W[(k + 1) * Hsz + h];
        __nv_bfloat16 hi = __float2bfloat16(w);
        g_Whi[i] = hi;
        g_Wlo[i] = __float2bfloat16(w - __bfloat162float(hi));
    }
}

// ---------- main persistent kernel ----------
__global__ __launch_bounds__(NTHR, 1)
void lstm_kernel(const float* __restrict__ Cprev,
                 const float* __restrict__ Wi, const float* __restrict__ bi,
                 const float* __restrict__ Wf, const float* __restrict__ bf,
                 const float* __restrict__ Wc, const float* __restrict__ bc,
                 const float* __restrict__ Wo, const float* __restrict__ bo,
                 float* __restrict__ out)
{
    extern __shared__ char smem[];
    const uint32_t sb = smem_u32(smem);
    float* parts = (float*)(smem + SM_PARTS);
    float* Cs    = (float*)(smem + SM_CS);
    float* W0s   = (float*)(smem + SM_W0S);
    float* Bss   = (float*)(smem + SM_BS);

    const int tid  = threadIdx.x;
    const int warp = tid >> 5;
    const int lane = tid & 31;
    const int cta  = blockIdx.x;
    const int b_off = (cta & 1) * 64;
    const int h_off = (cta >> 1) * 8;

    // W0 / bias
    if (tid < 32) {
        int h = h_off + (tid >> 2), g = tid & 3;
        const float* W = (g == 0) ? Wi : (g == 1) ? Wf : (g == 2) ? Wc : Wo;
        const float* B = (g == 0) ? bi : (g == 1) ? bf : (g == 2) ? bc : bo;
        W0s[tid] = W[h];
        Bss[tid] = B[h];
    }

    // one-time B tiles: 32 rows (gc) x 512 k bf16 hi/lo, chunk-swizzled
    {
        int r  = tid >> 4;                 // gc row 0..31
        int cj = tid & 15;
        int n  = (h_off + (r >> 2)) * 4 + (r & 3);
#pragma unroll
        for (int j = 0; j < 4; ++j) {
            int chunk = cj + 16 * j;       // 16B chunk index (8 bf16)
            uint32_t off = (uint32_t)r * 1024 + (uint32_t)((chunk ^ (r & 7)) << 4);
            uint4 vh = *(const uint4*)&g_Whi[n * 512 + chunk * 8];
            uint4 vl = *(const uint4*)&g_Wlo[n * 512 + chunk * 8];
            sts4(sb + SM_BHI + off, vh.x, vh.y, vh.z, vh.w);
            sts4(sb + SM_BLO + off, vl.x, vl.y, vl.z, vl.w);
        }
    }

    // epilogue / staging mappings
    const int eb  = tid >> 3;              // local batch 0..63
    const int ehl = tid & 7;               // local h 0..7
    const int cj8 = tid & 7;               // staging chunk base

    // C state to smem: Cs[b][hl]
    Cs[eb * 8 + ehl] = Cprev[(b_off + eb) * Hsz + h_off + ehl];

    // staging addresses: thread stages row eb (8 chunks hi + 8 lo)
    const uint32_t adst = sb + SM_AHI + (uint32_t)eb * 1024;
    const int      srx  = eb & 7;
    const char* srcH0 = (const char*)&g_Hhi[0][b_off + eb][0];
    const char* srcL0 = (const char*)&g_Hlo[0][b_off + eb][0];
    const size_t hstride = (size_t)Bsz * Hsz * sizeof(__nv_bfloat16);

    // GEMM warp tile: mt = rows 16mt.., nt = cols 8nt..
    const int mt = warp & 3;
    const int nt = warp >> 2;
    const int arow = mt * 16 + (lane & 7) + ((lane >> 3) & 1) * 8;
    const uint32_t abase = sb + SM_AHI + (uint32_t)arow * 1024;
    const int arx = arow & 7;
    const int ac0 = (lane >> 4) & 1;
    const int brow = nt * 8 + (lane & 7);
    const uint32_t bbase = sb + SM_BHI + (uint32_t)brow * 1024;
    const int brx = brow & 7;
    const int bsel = (lane >> 3) & 3;

    // frag store coords (xor-swizzled parts cols)
    const int fr0 = mt * 16 + (lane >> 2);
    const int fc  = nt * 8 + (lane & 3) * 2;
    const uint32_t fo0 = sb + SM_PARTS + (uint32_t)fr0 * 128
                       + (uint32_t)((fc ^ ((fr0 & 3) << 3)) << 2);

    float Hn8 = 0.f, Cn8 = 0.f;

    __syncthreads();

    int cur = 0;
    for (int t = 0; t < Ssz; ++t) {
        // ---- stage A hi/lo via cp.async (swizzled 16B chunks, no math) ----
        {
            const char* sh = srcH0 + (size_t)cur * hstride;
            const char* sl = srcL0 + (size_t)cur * hstride;
#pragma unroll
            for (int j = 0; j < 8; ++j) {
                int chunk = cj8 + 8 * j;
                uint32_t off = (uint32_t)((chunk ^ srx) << 4);
                cp16(adst + off,         sh + chunk * 16);
                cp16(adst + 65536 + off, sl + chunk * 16);
            }
            cp_commit_wait0();
        }
        __syncthreads();

        // ---- GEMM: 16 iterations x 2 k-steps, 3-pass bf16 split ----
        float c0 = 0.f, c1 = 0.f, c2 = 0.f, c3 = 0.f;
#pragma unroll 4
        for (int ks2 = 0; ks2 < 16; ++ks2) {
            uint32_t a0h, a1h, a2h, a3h, a0l, a1l, a2l, a3l;
            uint32_t bh0, bh1, bh2, bh3, bl0, bl1, bl2, bl3;
            uint32_t boff = bbase + (uint32_t)(((ks2 * 4 + bsel) ^ brx) << 4);
            ldsm4(bh0, bh1, bh2, bh3, boff);
            ldsm4(bl0, bl1, bl2, bl3, boff + 32768);
            // even k-step
            uint32_t ao0 = abase + (uint32_t)(((ks2 * 4 + ac0) ^ arx) << 4);
            ldsm4(a0h, a1h, a2h, a3h, ao0);
            ldsm4(a0l, a1l, a2l, a3l, ao0 + 65536);
            mma16816(c0, c1, c2, c3, a0h, a1h, a2h, a3h, bh0, bh1);
            mma16816(c0, c1, c2, c3, a0h, a1h, a2h, a3h, bl0, bl1);
            mma16816(c0, c1, c2, c3, a0l, a1l, a2l, a3l, bh0, bh1);
            // odd k-step
            uint32_t ao1 = abase + (uint32_t)(((ks2 * 4 + 2 + ac0) ^ arx) << 4);
            ldsm4(a0h, a1h, a2h, a3h, ao1);
            ldsm4(a0l, a1l, a2l, a3l, ao1 + 65536);
            mma16816(c0, c1, c2, c3, a0h, a1h, a2h, a3h, bh2, bh3);
            mma16816(c0, c1, c2, c3, a0h, a1h, a2h, a3h, bl2, bl3);
            mma16816(c0, c1, c2, c3, a0l, a1l, a2l, a3l, bh2, bh3);
        }

        // frag -> parts (xor-swizzled)
        asm volatile("st.shared.v2.f32 [%0], {%1,%2};" :: "r"(fo0), "f"(c0), "f"(c1));
        asm volatile("st.shared.v2.f32 [%0], {%1,%2};" :: "r"(fo0 + 8 * 128), "f"(c2), "f"(c3));
        __syncthreads();

        // ---- distributed epilogue: thread owns (eb, ehl) ----
        {
            float xa = g_xT[t][b_off + eb];
            const int sw = (eb & 3) << 3;
            float g0 = parts[eb * 32 + ((ehl * 4 + 0) ^ sw)];
            float g1 = parts[eb * 32 + ((ehl * 4 + 1) ^ sw)];
            float g2 = parts[eb * 32 + ((ehl * 4 + 2) ^ sw)];
            float g3 = parts[eb * 32 + ((ehl * 4 + 3) ^ sw)];
            int gc = ehl * 4;
            float gi  = fmaf(xa, W0s[gc + 0], g0 + Bss[gc + 0]);
            float gf  = fmaf(xa, W0s[gc + 1], g1 + Bss[gc + 1]);
            float gch = fmaf(xa, W0s[gc + 2], g2 + Bss[gc + 2]);
            float go  = fmaf(xa, W0s[gc + 3], g3 + Bss[gc + 3]);
            float Cold = Cs[eb * 8 + ehl];
            float I  = sigmoidf_(gi);
            float F  = sigmoidf_(gf);
            float Ch = tanhf_(gch);
            float Cn = F * Cold + I * Ch;
            float Hv = go * tanhf_(Cn);        // O has no sigmoid (faithful)
            Cs[eb * 8 + ehl] = Cn;
            // produce bf16 hi/lo split at the source
            __nv_bfloat16 hi = __float2bfloat16(Hv);
            __nv_bfloat16 lo = __float2bfloat16(Hv - __bfloat162float(hi));
            g_Hhi[cur ^ 1][b_off + eb][h_off + ehl] = hi;
            g_Hlo[cur ^ 1][b_off + eb][h_off + ehl] = lo;
            Hn8 = Hv; Cn8 = Cn;
        }

        grid_barrier((unsigned)(t + 1) * NBLK);
        cur ^= 1;
    }

    // outputs: (H, H, C), each [B][HID]
    {
        int base = (b_off + eb) * Hsz + h_off + ehl;
        out[base]                 = Hn8;
        out[Bsz * Hsz + base]     = Hn8;
        out[2 * Bsz * Hsz + base] = Cn8;
    }
}

extern "C" void kernel_launch(void* const* d_in, const int* in_sizes, int n_in,
                              void* d_out, int out_size) {
    (void)in_sizes; (void)n_in; (void)out_size;
    const float* x  = (const float*)d_in[0];
    const float* Hp = (const float*)d_in[1];
    const float* Cp = (const float*)d_in[2];
    const float* Wi = (const float*)d_in[3];
    const float* bi = (const float*)d_in[4];
    const float* Wf = (const float*)d_in[5];
    const float* bf = (const float*)d_in[6];
    const float* Wc = (const float*)d_in[7];
    const float* bc = (const float*)d_in[8];
    const float* Wo = (const float*)d_in[9];
    const float* bo = (const float*)d_in[10];

    cudaFuncSetAttribute(lstm_kernel,
                         cudaFuncAttributeMaxDynamicSharedMemorySize, SM_TOTAL);

    lstm_init_kernel<<<(2048 * 512 + 255) / 256, 256>>>(Hp, x, Wi, Wf, Wc, Wo);
    lstm_kernel<<<NBLK, NTHR, SM_TOTAL>>>(Cp, Wi, bi, Wf, bf, Wc, bc,
                                          Wo, bo, (float*)d_out);
}

// round 15
// speedup vs baseline: 2.5123x; 1.0260x over previous
#include <cuda_runtime.h>
#include <cuda_bf16.h>
#include <cstdint>

#define Bsz  128
#define Ssz  512
#define Hsz  512
#define NBLK 128
#define NTHR 512

// smem byte offsets
#define SM_AHI   0         // 64 rows x 1024B  (A hi bf16, chunk-swizzled)
#define SM_ALO   65536     // 64KB
#define SM_BHI   131072    // 32 rows x 1024B  (B hi)
#define SM_BLO   163840    // 32KB
#define SM_PARTS 196608    // 64 x 32 fp32 (8KB), xor-swizzled cols
#define SM_CS    204800    // 64 x 8 fp32 C state (2KB)
#define SM_W0S   206848    // 32 floats
#define SM_BS    206976    // 32 floats
#define SM_TOTAL 207104

// Persistent device state (no allocations allowed)
__device__ __nv_bfloat16 g_Hhi[2][Bsz][Hsz];    // H split hi, [b][h]
__device__ __nv_bfloat16 g_Hlo[2][Bsz][Hsz];    // H split lo
__device__ float         g_xT[Ssz][Bsz];
__device__ unsigned      g_bar;
__device__ __nv_bfloat16 g_Whi[2048 * 512];     // [n_glob = h*4+g][k]
__device__ __nv_bfloat16 g_Wlo[2048 * 512];

__device__ __forceinline__ uint32_t smem_u32(const void* p) {
    uint32_t a;
    asm("{ .reg .u64 t; cvta.to.shared.u64 t, %1; cvt.u32.u64 %0, t; }"
        : "=r"(a) : "l"(p));
    return a;
}
__device__ __forceinline__ float sigmoidf_(float v) {
    return __fdividef(1.0f, 1.0f + __expf(-v));
}
__device__ __forceinline__ float tanhf_(float v) {
    float x = fminf(fmaxf(v, -15.0f), 15.0f);
    float t = __expf(2.0f * x);
    return __fdividef(t - 1.0f, t + 1.0f);
}
__device__ __forceinline__ void ldsm4(uint32_t& r0, uint32_t& r1,
                                      uint32_t& r2, uint32_t& r3, uint32_t a) {
    asm volatile("ldmatrix.sync.aligned.m8n8.x4.shared.b16 {%0,%1,%2,%3}, [%4];"
                 : "=r"(r0), "=r"(r1), "=r"(r2), "=r"(r3) : "r"(a));
}
__device__ __forceinline__ void mma16816(float& c0, float& c1, float& c2, float& c3,
                                         uint32_t a0, uint32_t a1, uint32_t a2, uint32_t a3,
                                         uint32_t b0, uint32_t b1) {
    asm volatile(
        "mma.sync.aligned.m16n8k16.row.col.f32.bf16.bf16.f32 "
        "{%0,%1,%2,%3}, {%4,%5,%6,%7}, {%8,%9}, {%0,%1,%2,%3};"
        : "+f"(c0), "+f"(c1), "+f"(c2), "+f"(c3)
        : "r"(a0), "r"(a1), "r"(a2), "r"(a3), "r"(b0), "r"(b1));
}
__device__ __forceinline__ void sts4(uint32_t addr, uint32_t v0, uint32_t v1,
                                     uint32_t v2, uint32_t v3) {
    asm volatile("st.shared.v4.b32 [%0], {%1,%2,%3,%4};"
                 :: "r"(addr), "r"(v0), "r"(v1), "r"(v2), "r"(v3));
}
__device__ __forceinline__ void cp16(uint32_t dst_smem, const void* src) {
    asm volatile("cp.async.cg.shared.global [%0], [%1], 16;"
                 :: "r"(dst_smem), "l"(src));
}
__device__ __forceinline__ void cp_commit() {
    asm volatile("cp.async.commit_group;");
}
template<int N> __device__ __forceinline__ void cp_wait() {
    asm volatile("cp.async.wait_group %0;" :: "n"(N));
}
__device__ __forceinline__ void grid_barrier(unsigned target) {
    __syncthreads();
    if (threadIdx.x == 0) {
        asm volatile("red.release.gpu.global.add.u32 [%0], 1;"
                     :: "l"(&g_bar) : "memory");
        unsigned v;
        do {
            asm volatile("ld.acquire.gpu.global.u32 %0, [%1];"
                         : "=r"(v) : "l"(&g_bar) : "memory");
        } while (v < target);
    }
    __syncthreads();
}

// ---------- init: barrier, H hi/lo split, x transpose, W hi/lo split ----------
__global__ void lstm_init_kernel(const float* __restrict__ Hprev,
                                 const float* __restrict__ x,
                                 const float* __restrict__ Wi,
                                 const float* __restrict__ Wf,
                                 const float* __restrict__ Wc,
                                 const float* __restrict__ Wo) {
    int i = blockIdx.x * blockDim.x + threadIdx.x;
    if (i == 0) g_bar = 0;
    if (i < Bsz * Hsz) {                       // H_prev [b][h] -> hi/lo bf16
        float v = Hprev[i];
        __nv_bfloat16 hi = __float2bfloat16(v);
        g_Hhi[0][i >> 9][i & 511] = hi;
        g_Hlo[0][i >> 9][i & 511] = __float2bfloat16(v - __bfloat162float(hi));
    }
    if (i < Bsz * Ssz) {                       // x -> [t][b]
        int t = i >> 7, b = i & 127;
        g_xT[t][b] = x[b * Ssz + t];
    }
    if (i < 2048 * 512) {
        int n = i >> 9, k = i & 511;
        int h = n >> 2, g = n & 3;
        const float* W = (g == 0) ? Wi : (g == 1) ? Wf : (g == 2) ? Wc : Wo;
        float w = W[(k + 1) * Hsz + h];
        __nv_bfloat16 hi = __float2bfloat16(w);
        g_Whi[i] = hi;
        g_Wlo[i] = __float2bfloat16(w - __bfloat162float(hi));
    }
}

// ---------- main persistent kernel ----------
__global__ __launch_bounds__(NTHR, 1)
void lstm_kernel(const float* __restrict__ Cprev,
                 const float* __restrict__ Wi, const float* __restrict__ bi,
                 const float* __restrict__ Wf, const float* __restrict__ bf,
                 const float* __restrict__ Wc, const float* __restrict__ bc,
                 const float* __restrict__ Wo, const float* __restrict__ bo,
                 float* __restrict__ out)
{
    extern __shared__ char smem[];
    const uint32_t sb = smem_u32(smem);
    float* parts = (float*)(smem + SM_PARTS);
    float* Cs    = (float*)(smem + SM_CS);
    float* W0s   = (float*)(smem + SM_W0S);
    float* Bss   = (float*)(smem + SM_BS);

    const int tid  = threadIdx.x;
    const int warp = tid >> 5;
    const int lane = tid & 31;
    const int cta  = blockIdx.x;
    const int b_off = (cta & 1) * 64;
    const int h_off = (cta >> 1) * 8;

    // W0 / bias
    if (tid < 32) {
        int h = h_off + (tid >> 2), g = tid & 3;
        const float* W = (g == 0) ? Wi : (g == 1) ? Wf : (g == 2) ? Wc : Wo;
        const float* B = (g == 0) ? bi : (g == 1) ? bf : (g == 2) ? bc : bo;
        W0s[tid] = W[h];
        Bss[tid] = B[h];
    }

    // one-time B tiles: 32 rows (gc) x 512 k bf16 hi/lo, chunk-swizzled
    {
        int r  = tid >> 4;                 // gc row 0..31
        int cj = tid & 15;
        int n  = (h_off + (r >> 2)) * 4 + (r & 3);
#pragma unroll
        for (int j = 0; j < 4; ++j) {
            int chunk = cj + 16 * j;       // 16B chunk index (8 bf16)
            uint32_t off = (uint32_t)r * 1024 + (uint32_t)((chunk ^ (r & 7)) << 4);
            uint4 vh = *(const uint4*)&g_Whi[n * 512 + chunk * 8];
            uint4 vl = *(const uint4*)&g_Wlo[n * 512 + chunk * 8];
            sts4(sb + SM_BHI + off, vh.x, vh.y, vh.z, vh.w);
            sts4(sb + SM_BLO + off, vl.x, vl.y, vl.z, vl.w);
        }
    }

    // epilogue / staging mappings
    const int eb  = tid >> 3;              // local batch 0..63
    const int ehl = tid & 7;               // local h 0..7
    const int cj8 = tid & 7;               // staging chunk base

    // C state to smem: Cs[b][hl]
    Cs[eb * 8 + ehl] = Cprev[(b_off + eb) * Hsz + h_off + ehl];

    // staging addresses: thread stages row eb (8 chunks hi + 8 lo)
    const uint32_t adst = sb + SM_AHI + (uint32_t)eb * 1024;
    const int      srx  = eb & 7;
    const char* srcH0 = (const char*)&g_Hhi[0][b_off + eb][0];
    const char* srcL0 = (const char*)&g_Hlo[0][b_off + eb][0];
    const size_t hstride = (size_t)Bsz * Hsz * sizeof(__nv_bfloat16);

    // GEMM warp tile: mt = rows 16mt.., nt = cols 8nt..
    const int mt = warp & 3;
    const int nt = warp >> 2;
    const int arow = mt * 16 + (lane & 7) + ((lane >> 3) & 1) * 8;
    const uint32_t abase = sb + SM_AHI + (uint32_t)arow * 1024;
    const int arx = arow & 7;
    const int ac0 = (lane >> 4) & 1;
    const int brow = nt * 8 + (lane & 7);
    const uint32_t bbase = sb + SM_BHI + (uint32_t)brow * 1024;
    const int brx = brow & 7;
    const int bsel = (lane >> 3) & 3;

    // frag store coords (xor-swizzled parts cols)
    const int fr0 = mt * 16 + (lane >> 2);
    const int fc  = nt * 8 + (lane & 3) * 2;
    const uint32_t fo0 = sb + SM_PARTS + (uint32_t)fr0 * 128
                       + (uint32_t)((fc ^ ((fr0 & 3) << 3)) << 2);

    float Hn8 = 0.f, Cn8 = 0.f;

    __syncthreads();

    int cur = 0;
    for (int t = 0; t < Ssz; ++t) {
        // ---- stage A hi/lo via cp.async: TWO k-half groups ----
        {
            const char* sh = srcH0 + (size_t)cur * hstride;
            const char* sl = srcL0 + (size_t)cur * hstride;
#pragma unroll
            for (int j = 0; j < 4; ++j) {          // k 0..255
                int chunk = cj8 + 8 * j;
                uint32_t off = (uint32_t)((chunk ^ srx) << 4);
                cp16(adst + off,         sh + chunk * 16);
                cp16(adst + 65536 + off, sl + chunk * 16);
            }
            cp_commit();
#pragma unroll
            for (int j = 4; j < 8; ++j) {          // k 256..511
                int chunk = cj8 + 8 * j;
                uint32_t off = (uint32_t)((chunk ^ srx) << 4);
                cp16(adst + off,         sh + chunk * 16);
                cp16(adst + 65536 + off, sl + chunk * 16);
            }
            cp_commit();
        }

        // prefetch x while staging flies (latency hides under GEMM)
        float xa = __ldcg(&g_xT[t][b_off + eb]);

        float c0 = 0.f, c1 = 0.f, c2 = 0.f, c3 = 0.f;
        // ---- GEMM in two k-halves, each pipelined against staging ----
#pragma unroll
        for (int hf = 0; hf < 2; ++hf) {
            if (hf == 0) cp_wait<1>();
            else         cp_wait<0>();
            __syncthreads();
#pragma unroll 4
            for (int q = 0; q < 8; ++q) {
                int ks2 = hf * 8 + q;
                uint32_t a0h, a1h, a2h, a3h, a0l, a1l, a2l, a3l;
                uint32_t bh0, bh1, bh2, bh3, bl0, bl1, bl2, bl3;
                uint32_t boff = bbase + (uint32_t)(((ks2 * 4 + bsel) ^ brx) << 4);
                ldsm4(bh0, bh1, bh2, bh3, boff);
                ldsm4(bl0, bl1, bl2, bl3, boff + 32768);
                // even k-step
                uint32_t ao0 = abase + (uint32_t)(((ks2 * 4 + ac0) ^ arx) << 4);
                ldsm4(a0h, a1h, a2h, a3h, ao0);
                ldsm4(a0l, a1l, a2l, a3l, ao0 + 65536);
                mma16816(c0, c1, c2, c3, a0h, a1h, a2h, a3h, bh0, bh1);
                mma16816(c0, c1, c2, c3, a0h, a1h, a2h, a3h, bl0, bl1);
                mma16816(c0, c1, c2, c3, a0l, a1l, a2l, a3l, bh0, bh1);
                // odd k-step
                uint32_t ao1 = abase + (uint32_t)(((ks2 * 4 + 2 + ac0) ^ arx) << 4);
                ldsm4(a0h, a1h, a2h, a3h, ao1);
                ldsm4(a0l, a1l, a2l, a3l, ao1 + 65536);
                mma16816(c0, c1, c2, c3, a0h, a1h, a2h, a3h, bh2, bh3);
                mma16816(c0, c1, c2, c3, a0h, a1h, a2h, a3h, bl2, bl3);
                mma16816(c0, c1, c2, c3, a0l, a1l, a2l, a3l, bh2, bh3);
            }
        }

        // frag -> parts (xor-swizzled)
        asm volatile("st.shared.v2.f32 [%0], {%1,%2};" :: "r"(fo0), "f"(c0), "f"(c1));
        asm volatile("st.shared.v2.f32 [%0], {%1,%2};" :: "r"(fo0 + 8 * 128), "f"(c2), "f"(c3));
        __syncthreads();

        // ---- distributed epilogue: thread owns (eb, ehl) ----
        {
            const int sw = (eb & 3) << 3;
            float g0 = parts[eb * 32 + ((ehl * 4 + 0) ^ sw)];
            float g1 = parts[eb * 32 + ((ehl * 4 + 1) ^ sw)];
            float g2 = parts[eb * 32 + ((ehl * 4 + 2) ^ sw)];
            float g3 = parts[eb * 32 + ((ehl * 4 + 3) ^ sw)];
            int gc = ehl * 4;
            float gi  = fmaf(xa, W0s[gc + 0], g0 + Bss[gc + 0]);
            float gf  = fmaf(xa, W0s[gc + 1], g1 + Bss[gc + 1]);
            float gch = fmaf(xa, W0s[gc + 2], g2 + Bss[gc + 2]);
            float go  = fmaf(xa, W0s[gc + 3], g3 + Bss[gc + 3]);
            float Cold = Cs[eb * 8 + ehl];
            float I  = sigmoidf_(gi);
            float F  = sigmoidf_(gf);
            float Ch = tanhf_(gch);
            float Cn = F * Cold + I * Ch;
            float Hv = go * tanhf_(Cn);        // O has no sigmoid (faithful)
            // publish H hi/lo immediately (stores fly while we finish bookkeeping)
            __nv_bfloat16 hi = __float2bfloat16(Hv);
            __nv_bfloat16 lo = __float2bfloat16(Hv - __bfloat162float(hi));
            g_Hhi[cur ^ 1][b_off + eb][h_off + ehl] = hi;
            g_Hlo[cur ^ 1][b_off + eb][h_off + ehl] = lo;
            Cs[eb * 8 + ehl] = Cn;
            Hn8 = Hv; Cn8 = Cn;
        }

        grid_barrier((unsigned)(t + 1) * NBLK);
        cur ^= 1;
    }

    // outputs: (H, H, C), each [B][HID]
    {
        int base = (b_off + eb) * Hsz + h_off + ehl;
        out[base]                 = Hn8;
        out[Bsz * Hsz + base]     = Hn8;
        out[2 * Bsz * Hsz + base] = Cn8;
    }
}

extern "C" void kernel_launch(void* const* d_in, const int* in_sizes, int n_in,
                              void* d_out, int out_size) {
    (void)in_sizes; (void)n_in; (void)out_size;
    const float* x  = (const float*)d_in[0];
    const float* Hp = (const float*)d_in[1];
    const float* Cp = (const float*)d_in[2];
    const float* Wi = (const float*)d_in[3];
    const float* bi = (const float*)d_in[4];
    const float* Wf = (const float*)d_in[5];
    const float* bf = (const float*)d_in[6];
    const float* Wc = (const float*)d_in[7];
    const float* bc = (const float*)d_in[8];
    const float* Wo = (const float*)d_in[9];
    const float* bo = (const float*)d_in[10];

    cudaFuncSetAttribute(lstm_kernel,
                         cudaFuncAttributeMaxDynamicSharedMemorySize, SM_TOTAL);

    lstm_init_kernel<<<(2048 * 512 + 255) / 256, 256>>>(Hp, x, Wi, Wf, Wc, Wo);
    lstm_kernel<<<NBLK, NTHR, SM_TOTAL>>>(Cp, Wi, bi, Wf, bf, Wc, bc,
                                          Wo, bo, (float*)d_out);
}

// round 16
// speedup vs baseline: 2.6854x; 1.0689x over previous
#include <cuda_runtime.h>
#include <cuda_bf16.h>
#include <cstdint>

#define Bsz  128
#define Ssz  512
#define Hsz  512
#define NBLK 128
#define NTHR 512

// smem byte offsets (CTA = 32 batches x 64 gate-cols)
#define SM_AHI   0         // 32 rows x 1024B  (A hi bf16, chunk-swizzled)
#define SM_ALO   32768
#define SM_BHI   65536     // 64 rows x 1024B  (B hi)
#define SM_BLO   131072
#define SM_PARTS 196608    // 32 x 64 fp32 (8KB), xor-swizzled cols
#define SM_CS    204800    // 32 x 16 fp32 C state (2KB)
#define SM_W0S   206848    // 64 floats
#define SM_BS    207104    // 64 floats
#define SM_TOTAL 207360

// Persistent device state (no allocations allowed)
__device__ __nv_bfloat16 g_Hhi[2][Bsz][Hsz];    // H split hi, [b][h]
__device__ __nv_bfloat16 g_Hlo[2][Bsz][Hsz];    // H split lo
__device__ float         g_xT[Ssz][Bsz];
__device__ unsigned      g_bar;
__device__ __nv_bfloat16 g_Whi[2048 * 512];     // [n_glob = h*4+g][k]
__device__ __nv_bfloat16 g_Wlo[2048 * 512];

__device__ __forceinline__ uint32_t smem_u32(const void* p) {
    uint32_t a;
    asm("{ .reg .u64 t; cvta.to.shared.u64 t, %1; cvt.u32.u64 %0, t; }"
        : "=r"(a) : "l"(p));
    return a;
}
__device__ __forceinline__ float sigmoidf_(float v) {
    return __fdividef(1.0f, 1.0f + __expf(-v));
}
__device__ __forceinline__ float tanhf_(float v) {
    float x = fminf(fmaxf(v, -15.0f), 15.0f);
    float t = __expf(2.0f * x);
    return __fdividef(t - 1.0f, t + 1.0f);
}
__device__ __forceinline__ void ldsm4(uint32_t& r0, uint32_t& r1,
                                      uint32_t& r2, uint32_t& r3, uint32_t a) {
    asm volatile("ldmatrix.sync.aligned.m8n8.x4.shared.b16 {%0,%1,%2,%3}, [%4];"
                 : "=r"(r0), "=r"(r1), "=r"(r2), "=r"(r3) : "r"(a));
}
__device__ __forceinline__ void mma16816(float* c,
                                         uint32_t a0, uint32_t a1, uint32_t a2, uint32_t a3,
                                         uint32_t b0, uint32_t b1) {
    asm volatile(
        "mma.sync.aligned.m16n8k16.row.col.f32.bf16.bf16.f32 "
        "{%0,%1,%2,%3}, {%4,%5,%6,%7}, {%8,%9}, {%0,%1,%2,%3};"
        : "+f"(c[0]), "+f"(c[1]), "+f"(c[2]), "+f"(c[3])
        : "r"(a0), "r"(a1), "r"(a2), "r"(a3), "r"(b0), "r"(b1));
}
__device__ __forceinline__ void sts4(uint32_t addr, uint32_t v0, uint32_t v1,
                                     uint32_t v2, uint32_t v3) {
    asm volatile("st.shared.v4.b32 [%0], {%1,%2,%3,%4};"
                 :: "r"(addr), "r"(v0), "r"(v1), "r"(v2), "r"(v3));
}
__device__ __forceinline__ void cp16(uint32_t dst_smem, const void* src) {
    asm volatile("cp.async.cg.shared.global [%0], [%1], 16;"
                 :: "r"(dst_smem), "l"(src));
}
__device__ __forceinline__ void cp_commit() {
    asm volatile("cp.async.commit_group;");
}
template<int N> __device__ __forceinline__ void cp_wait() {
    asm volatile("cp.async.wait_group %0;" :: "n"(N));
}
__device__ __forceinline__ void grid_barrier(unsigned target) {
    __syncthreads();
    if (threadIdx.x == 0) {
        asm volatile("red.release.gpu.global.add.u32 [%0], 1;"
                     :: "l"(&g_bar) : "memory");
        unsigned v;
        do {
            asm volatile("ld.acquire.gpu.global.u32 %0, [%1];"
                         : "=r"(v) : "l"(&g_bar) : "memory");
        } while (v < target);
    }
    __syncthreads();
}

// ---------- init: barrier, H hi/lo split, x transpose, W hi/lo split ----------
__global__ void lstm_init_kernel(const float* __restrict__ Hprev,
                                 const float* __restrict__ x,
                                 const float* __restrict__ Wi,
                                 const float* __restrict__ Wf,
                                 const float* __restrict__ Wc,
                                 const float* __restrict__ Wo) {
    int i = blockIdx.x * blockDim.x + threadIdx.x;
    if (i == 0) g_bar = 0;
    if (i < Bsz * Hsz) {                       // H_prev [b][h] -> hi/lo bf16
        float v = Hprev[i];
        __nv_bfloat16 hi = __float2bfloat16(v);
        g_Hhi[0][i >> 9][i & 511] = hi;
        g_Hlo[0][i >> 9][i & 511] = __float2bfloat16(v - __bfloat162float(hi));
    }
    if (i < Bsz * Ssz) {                       // x -> [t][b]
        int t = i >> 7, b = i & 127;
        g_xT[t][b] = x[b * Ssz + t];
    }
    if (i < 2048 * 512) {
        int n = i >> 9, k = i & 511;
        int h = n >> 2, g = n & 3;
        const float* W = (g == 0) ? Wi : (g == 1) ? Wf : (g == 2) ? Wc : Wo;
        float w = W[(k + 1) * Hsz + h];
        __nv_bfloat16 hi = __float2bfloat16(w);
        g_Whi[i] = hi;
        g_Wlo[i] = __float2bfloat16(w - __bfloat162float(hi));
    }
}

// ---------- main persistent kernel ----------
__global__ __launch_bounds__(NTHR, 1)
void lstm_kernel(const float* __restrict__ Cprev,
                 const float* __restrict__ Wi, const float* __restrict__ bi,
                 const float* __restrict__ Wf, const float* __restrict__ bf,
                 const float* __restrict__ Wc, const float* __restrict__ bc,
                 const float* __restrict__ Wo, const float* __restrict__ bo,
                 float* __restrict__ out)
{
    extern __shared__ char smem[];
    const uint32_t sb = smem_u32(smem);
    float* parts = (float*)(smem + SM_PARTS);
    float* Cs    = (float*)(smem + SM_CS);
    float* W0s   = (float*)(smem + SM_W0S);
    float* Bss   = (float*)(smem + SM_BS);

    const int tid  = threadIdx.x;
    const int warp = tid >> 5;
    const int lane = tid & 31;
    const int cta  = blockIdx.x;
    const int b_off = (cta & 3) * 32;          // batch quarter
    const int h_off = (cta >> 2) * 16;         // 16 h-units = 64 gate cols

    // W0 / bias (64 gate cols)
    if (tid < 64) {
        int h = h_off + (tid >> 2), g = tid & 3;
        const float* W = (g == 0) ? Wi : (g == 1) ? Wf : (g == 2) ? Wc : Wo;
        const float* B = (g == 0) ? bi : (g == 1) ? bf : (g == 2) ? bc : bo;
        W0s[tid] = W[h];
        Bss[tid] = B[h];
    }

    // one-time B tiles: 64 rows (gc) x 512 k bf16 hi/lo, chunk-swizzled
    {
        int r  = tid >> 3;                 // gc row 0..63
        int cj = tid & 7;
        int n  = (h_off + (r >> 2)) * 4 + (r & 3);
#pragma unroll
        for (int j = 0; j < 8; ++j) {
            int chunk = cj + 8 * j;        // 16B chunk index (8 bf16)
            uint32_t off = (uint32_t)r * 1024 + (uint32_t)((chunk ^ (r & 7)) << 4);
            uint4 vh = *(const uint4*)&g_Whi[n * 512 + chunk * 8];
            uint4 vl = *(const uint4*)&g_Wlo[n * 512 + chunk * 8];
            sts4(sb + SM_BHI + off, vh.x, vh.y, vh.z, vh.w);
            sts4(sb + SM_BLO + off, vl.x, vl.y, vl.z, vl.w);
        }
    }

    // epilogue mapping: thread owns (eb 0..31, ehl 0..15)
    const int eb  = tid >> 4;
    const int ehl = tid & 15;

    // C state to smem
    Cs[eb * 16 + ehl] = Cprev[(b_off + eb) * Hsz + h_off + ehl];

    // staging: thread stages row sr, 4 hi + 4 lo chunks
    const int sr   = tid >> 4;             // batch row 0..31
    const int cj16 = tid & 15;
    const uint32_t adst = sb + SM_AHI + (uint32_t)sr * 1024;
    const int      srx  = sr & 7;
    const char* srcH0 = (const char*)&g_Hhi[0][b_off + sr][0];
    const char* srcL0 = (const char*)&g_Hlo[0][b_off + sr][0];
    const size_t hstride = (size_t)Bsz * Hsz * sizeof(__nv_bfloat16);

    // GEMM warp tile: mt = rows 16mt (0..1), nt = cols 8nt (0..7)
    const int mt = warp & 1;
    const int nt = warp >> 1;
    const int arow = mt * 16 + (lane & 7) + ((lane >> 3) & 1) * 8;
    const uint32_t abase = sb + SM_AHI + (uint32_t)arow * 1024;
    const int arx = arow & 7;
    const int ac0 = (lane >> 4) & 1;
    const int brow = nt * 8 + (lane & 7);
    const uint32_t bbase = sb + SM_BHI + (uint32_t)brow * 1024;
    const int brx = brow & 7;
    const int bsel = (lane >> 3) & 3;

    // frag store coords (xor-swizzled parts cols, row stride 64 floats)
    const int fr0 = mt * 16 + (lane >> 2);
    const int fc  = nt * 8 + (lane & 3) * 2;
    const uint32_t fo0 = sb + SM_PARTS + (uint32_t)fr0 * 256
                       + (uint32_t)((fc ^ ((fr0 & 3) << 3)) << 2);

    float Hn8 = 0.f, Cn8 = 0.f;

    __syncthreads();

    int cur = 0;
    for (int t = 0; t < Ssz; ++t) {
        // ---- stage A hi/lo via cp.async: two k-half groups ----
        {
            const char* sh = srcH0 + (size_t)cur * hstride;
            const char* sl = srcL0 + (size_t)cur * hstride;
#pragma unroll
            for (int j = 0; j < 2; ++j) {          // k 0..255
                int chunk = cj16 + 16 * j;
                uint32_t off = (uint32_t)((chunk ^ srx) << 4);
                cp16(adst + off,         sh + chunk * 16);
                cp16(adst + 32768 + off, sl + chunk * 16);
            }
            cp_commit();
#pragma unroll
            for (int j = 2; j < 4; ++j) {          // k 256..511
                int chunk = cj16 + 16 * j;
                uint32_t off = (uint32_t)((chunk ^ srx) << 4);
                cp16(adst + off,         sh + chunk * 16);
                cp16(adst + 32768 + off, sl + chunk * 16);
            }
            cp_commit();
        }

        // prefetch x while staging flies
        float xa = __ldcg(&g_xT[t][b_off + eb]);

        // 3 independent accumulator chains (hihi / hilo / lohi)
        float cA[4] = {0.f, 0.f, 0.f, 0.f};
        float cB[4] = {0.f, 0.f, 0.f, 0.f};
        float cC[4] = {0.f, 0.f, 0.f, 0.f};

#pragma unroll
        for (int hf = 0; hf < 2; ++hf) {
            if (hf == 0) cp_wait<1>();
            else         cp_wait<0>();
            __syncthreads();
#pragma unroll 4
            for (int q = 0; q < 8; ++q) {
                int ks2 = hf * 8 + q;
                uint32_t a0h, a1h, a2h, a3h, a0l, a1l, a2l, a3l;
                uint32_t bh0, bh1, bh2, bh3, bl0, bl1, bl2, bl3;
                uint32_t boff = bbase + (uint32_t)(((ks2 * 4 + bsel) ^ brx) << 4);
                ldsm4(bh0, bh1, bh2, bh3, boff);
                ldsm4(bl0, bl1, bl2, bl3, boff + 65536);
                // even k-step
                uint32_t ao0 = abase + (uint32_t)(((ks2 * 4 + ac0) ^ arx) << 4);
                ldsm4(a0h, a1h, a2h, a3h, ao0);
                ldsm4(a0l, a1l, a2l, a3l, ao0 + 32768);
                mma16816(cA, a0h, a1h, a2h, a3h, bh0, bh1);
                mma16816(cB, a0h, a1h, a2h, a3h, bl0, bl1);
                mma16816(cC, a0l, a1l, a2l, a3l, bh0, bh1);
                // odd k-step
                uint32_t ao1 = abase + (uint32_t)(((ks2 * 4 + 2 + ac0) ^ arx) << 4);
                ldsm4(a0h, a1h, a2h, a3h, ao1);
                ldsm4(a0l, a1l, a2l, a3l, ao1 + 32768);
                mma16816(cA, a0h, a1h, a2h, a3h, bh2, bh3);
                mma16816(cB, a0h, a1h, a2h, a3h, bl2, bl3);
                mma16816(cC, a0l, a1l, a2l, a3l, bh2, bh3);
            }
        }

        // combine chains, frag -> parts (xor-swizzled)
        {
            float c0 = cA[0] + cB[0] + cC[0];
            float c1 = cA[1] + cB[1] + cC[1];
            float c2 = cA[2] + cB[2] + cC[2];
            float c3 = cA[3] + cB[3] + cC[3];
            asm volatile("st.shared.v2.f32 [%0], {%1,%2};" :: "r"(fo0), "f"(c0), "f"(c1));
            asm volatile("st.shared.v2.f32 [%0], {%1,%2};" :: "r"(fo0 + 8 * 256), "f"(c2), "f"(c3));
        }
        __syncthreads();

        // ---- distributed epilogue: thread owns (eb, ehl) ----
        {
            const int sw = (eb & 3) << 3;
            float g0 = parts[eb * 64 + ((ehl * 4 + 0) ^ sw)];
            float g1 = parts[eb * 64 + ((ehl * 4 + 1) ^ sw)];
            float g2 = parts[eb * 64 + ((ehl * 4 + 2) ^ sw)];
            float g3 = parts[eb * 64 + ((ehl * 4 + 3) ^ sw)];
            int gc = ehl * 4;
            float gi  = fmaf(xa, W0s[gc + 0], g0 + Bss[gc + 0]);
            float gf  = fmaf(xa, W0s[gc + 1], g1 + Bss[gc + 1]);
            float gch = fmaf(xa, W0s[gc + 2], g2 + Bss[gc + 2]);
            float go  = fmaf(xa, W0s[gc + 3], g3 + Bss[gc + 3]);
            float Cold = Cs[eb * 16 + ehl];
            float I  = sigmoidf_(gi);
            float F  = sigmoidf_(gf);
            float Ch = tanhf_(gch);
            float Cn = F * Cold + I * Ch;
            float Hv = go * tanhf_(Cn);        // O has no sigmoid (faithful)
            __nv_bfloat16 hi = __float2bfloat16(Hv);
            __nv_bfloat16 lo = __float2bfloat16(Hv - __bfloat162float(hi));
            g_Hhi[cur ^ 1][b_off + eb][h_off + ehl] = hi;
            g_Hlo[cur ^ 1][b_off + eb][h_off + ehl] = lo;
            Cs[eb * 16 + ehl] = Cn;
            Hn8 = Hv; Cn8 = Cn;
        }

        grid_barrier((unsigned)(t + 1) * NBLK);
        cur ^= 1;
    }

    // outputs: (H, H, C), each [B][HID]
    {
        int base = (b_off + eb) * Hsz + h_off + ehl;
        out[base]                 = Hn8;
        out[Bsz * Hsz + base]     = Hn8;
        out[2 * Bsz * Hsz + base] = Cn8;
    }
}

extern "C" void kernel_launch(void* const* d_in, const int* in_sizes, int n_in,
                              void* d_out, int out_size) {
    (void)in_sizes; (void)n_in; (void)out_size;
    const float* x  = (const float*)d_in[0];
    const float* Hp = (const float*)d_in[1];
    const float* Cp = (const float*)d_in[2];
    const float* Wi = (const float*)d_in[3];
    const float* bi = (const float*)d_in[4];
    const float* Wf = (const float*)d_in[5];
    const float* bf = (const float*)d_in[6];
    const float* Wc = (const float*)d_in[7];
    const float* bc = (const float*)d_in[8];
    const float* Wo = (const float*)d_in[9];
    const float* bo = (const float*)d_in[10];

    cudaFuncSetAttribute(lstm_kernel,
                         cudaFuncAttributeMaxDynamicSharedMemorySize, SM_TOTAL);

    lstm_init_kernel<<<(2048 * 512 + 255) / 256, 256>>>(Hp, x, Wi, Wf, Wc, Wo);
    lstm_kernel<<<NBLK, NTHR, SM_TOTAL>>>(Cp, Wi, bi, Wf, bf, Wc, bc,
                                          Wo, bo, (float*)d_out);
}

// round 17
// speedup vs baseline: 2.7708x; 1.0318x over previous
#include <cuda_runtime.h>
#include <cuda_bf16.h>
#include <cstdint>

#define Bsz  128
#define Ssz  512
#define Hsz  512
#define NBLK 128
#define NTHR 512

// smem byte offsets (CTA = 32 batches x 64 gate-cols)
#define SM_AHI   0         // 32 rows x 1024B  (A hi bf16, chunk-swizzled)
#define SM_ALO   32768
#define SM_BHI   65536     // 64 rows x 1024B  (B hi)
#define SM_BLO   131072
#define SM_PARTS 196608    // 32 x 64 fp32 (8KB), xor-swizzled cols
#define SM_CS    204800    // 32 x 16 fp32 C state (2KB)
#define SM_W0S   206848    // 64 floats
#define SM_BS    207104    // 64 floats
#define SM_TOTAL 207360

// Persistent device state (no allocations allowed)
__device__ __nv_bfloat16 g_Hhi[2][Bsz][Hsz];    // H split hi, [b][h]
__device__ __nv_bfloat16 g_Hlo[2][Bsz][Hsz];    // H split lo
__device__ float         g_xT[Ssz][Bsz];
__device__ unsigned      g_barq[4 * 32];        // per-quarter barrier, 128B apart
__device__ __nv_bfloat16 g_Whi[2048 * 512];     // [n_glob = h*4+g][k]
__device__ __nv_bfloat16 g_Wlo[2048 * 512];

__device__ __forceinline__ uint32_t smem_u32(const void* p) {
    uint32_t a;
    asm("{ .reg .u64 t; cvta.to.shared.u64 t, %1; cvt.u32.u64 %0, t; }"
        : "=r"(a) : "l"(p));
    return a;
}
__device__ __forceinline__ float sigmoidf_(float v) {
    return __fdividef(1.0f, 1.0f + __expf(-v));
}
__device__ __forceinline__ float tanhf_(float v) {
    float x = fminf(fmaxf(v, -15.0f), 15.0f);
    float t = __expf(2.0f * x);
    return __fdividef(t - 1.0f, t + 1.0f);
}
__device__ __forceinline__ void ldsm4(uint32_t& r0, uint32_t& r1,
                                      uint32_t& r2, uint32_t& r3, uint32_t a) {
    asm volatile("ldmatrix.sync.aligned.m8n8.x4.shared.b16 {%0,%1,%2,%3}, [%4];"
                 : "=r"(r0), "=r"(r1), "=r"(r2), "=r"(r3) : "r"(a));
}
__device__ __forceinline__ void mma16816(float* c,
                                         uint32_t a0, uint32_t a1, uint32_t a2, uint32_t a3,
                                         uint32_t b0, uint32_t b1) {
    asm volatile(
        "mma.sync.aligned.m16n8k16.row.col.f32.bf16.bf16.f32 "
        "{%0,%1,%2,%3}, {%4,%5,%6,%7}, {%8,%9}, {%0,%1,%2,%3};"
        : "+f"(c[0]), "+f"(c[1]), "+f"(c[2]), "+f"(c[3])
        : "r"(a0), "r"(a1), "r"(a2), "r"(a3), "r"(b0), "r"(b1));
}
__device__ __forceinline__ void sts4(uint32_t addr, uint32_t v0, uint32_t v1,
                                     uint32_t v2, uint32_t v3) {
    asm volatile("st.shared.v4.b32 [%0], {%1,%2,%3,%4};"
                 :: "r"(addr), "r"(v0), "r"(v1), "r"(v2), "r"(v3));
}
__device__ __forceinline__ void cp16(uint32_t dst_smem, const void* src) {
    asm volatile("cp.async.cg.shared.global [%0], [%1], 16;"
                 :: "r"(dst_smem), "l"(src));
}
__device__ __forceinline__ void cp_commit() {
    asm volatile("cp.async.commit_group;");
}
template<int N> __device__ __forceinline__ void cp_wait() {
    asm volatile("cp.async.wait_group %0;" :: "n"(N));
}
// per-quarter grid barrier: 32 CTAs, own 128B-padded counter
__device__ __forceinline__ void quarter_barrier(unsigned target, unsigned* ctr) {
    __syncthreads();
    if (threadIdx.x == 0) {
        asm volatile("red.release.gpu.global.add.u32 [%0], 1;"
                     :: "l"(ctr) : "memory");
        unsigned v;
        do {
            asm volatile("ld.acquire.gpu.global.u32 %0, [%1];"
                         : "=r"(v) : "l"(ctr) : "memory");
        } while (v < target);
    }
    __syncthreads();
}

// ---------- init: barriers, H hi/lo split, x transpose, W hi/lo split ----------
__global__ void lstm_init_kernel(const float* __restrict__ Hprev,
                                 const float* __restrict__ x,
                                 const float* __restrict__ Wi,
                                 const float* __restrict__ Wf,
                                 const float* __restrict__ Wc,
                                 const float* __restrict__ Wo) {
    int i = blockIdx.x * blockDim.x + threadIdx.x;
    if (i < 4 * 32) g_barq[i] = 0;
    if (i < Bsz * Hsz) {                       // H_prev [b][h] -> hi/lo bf16
        float v = Hprev[i];
        __nv_bfloat16 hi = __float2bfloat16(v);
        g_Hhi[0][i >> 9][i & 511] = hi;
        g_Hlo[0][i >> 9][i & 511] = __float2bfloat16(v - __bfloat162float(hi));
    }
    if (i < Bsz * Ssz) {                       // x -> [t][b]
        int t = i >> 7, b = i & 127;
        g_xT[t][b] = x[b * Ssz + t];
    }
    if (i < 2048 * 512) {
        int n = i >> 9, k = i & 511;
        int h = n >> 2, g = n & 3;
        const float* W = (g == 0) ? Wi : (g == 1) ? Wf : (g == 2) ? Wc : Wo;
        float w = W[(k + 1) * Hsz + h];
        __nv_bfloat16 hi = __float2bfloat16(w);
        g_Whi[i] = hi;
        g_Wlo[i] = __float2bfloat16(w - __bfloat162float(hi));
    }
}

// ---------- main persistent kernel ----------
__global__ __launch_bounds__(NTHR, 1)
void lstm_kernel(const float* __restrict__ Cprev,
                 const float* __restrict__ Wi, const float* __restrict__ bi,
                 const float* __restrict__ Wf, const float* __restrict__ bf,
                 const float* __restrict__ Wc, const float* __restrict__ bc,
                 const float* __restrict__ Wo, const float* __restrict__ bo,
                 float* __restrict__ out)
{
    extern __shared__ char smem[];
    const uint32_t sb = smem_u32(smem);
    float* parts = (float*)(smem + SM_PARTS);
    float* Cs    = (float*)(smem + SM_CS);
    float* W0s   = (float*)(smem + SM_W0S);
    float* Bss   = (float*)(smem + SM_BS);

    const int tid  = threadIdx.x;
    const int warp = tid >> 5;
    const int lane = tid & 31;
    const int cta  = blockIdx.x;
    const int quarter = cta & 3;
    const int b_off = quarter * 32;            // batch quarter
    const int h_off = (cta >> 2) * 16;         // 16 h-units = 64 gate cols
    unsigned* qctr = &g_barq[quarter * 32];

    // W0 / bias (64 gate cols)
    if (tid < 64) {
        int h = h_off + (tid >> 2), g = tid & 3;
        const float* W = (g == 0) ? Wi : (g == 1) ? Wf : (g == 2) ? Wc : Wo;
        const float* B = (g == 0) ? bi : (g == 1) ? bf : (g == 2) ? bc : bo;
        W0s[tid] = W[h];
        Bss[tid] = B[h];
    }

    // one-time B tiles: 64 rows (gc) x 512 k bf16 hi/lo, chunk-swizzled
    {
        int r  = tid >> 3;                 // gc row 0..63
        int cj = tid & 7;
        int n  = (h_off + (r >> 2)) * 4 + (r & 3);
#pragma unroll
        for (int j = 0; j < 8; ++j) {
            int chunk = cj + 8 * j;        // 16B chunk index (8 bf16)
            uint32_t off = (uint32_t)r * 1024 + (uint32_t)((chunk ^ (r & 7)) << 4);
            uint4 vh = *(const uint4*)&g_Whi[n * 512 + chunk * 8];
            uint4 vl = *(const uint4*)&g_Wlo[n * 512 + chunk * 8];
            sts4(sb + SM_BHI + off, vh.x, vh.y, vh.z, vh.w);
            sts4(sb + SM_BLO + off, vl.x, vl.y, vl.z, vl.w);
        }
    }

    // epilogue mapping: thread owns (eb 0..31, ehl 0..15)
    const int eb  = tid >> 4;
    const int ehl = tid & 15;

    // C state to smem
    Cs[eb * 16 + ehl] = Cprev[(b_off + eb) * Hsz + h_off + ehl];

    // staging: thread stages row sr, 4 hi + 4 lo chunks
    const int sr   = tid >> 4;             // batch row 0..31
    const int cj16 = tid & 15;
    const uint32_t adst = sb + SM_AHI + (uint32_t)sr * 1024;
    const int      srx  = sr & 7;
    const char* srcH0 = (const char*)&g_Hhi[0][b_off + sr][0];
    const char* srcL0 = (const char*)&g_Hlo[0][b_off + sr][0];
    const size_t hstride = (size_t)Bsz * Hsz * sizeof(__nv_bfloat16);

    // GEMM warp tile: mt = rows 16mt (0..1), nt = cols 8nt (0..7)
    const int mt = warp & 1;
    const int nt = warp >> 1;
    const int arow = mt * 16 + (lane & 7) + ((lane >> 3) & 1) * 8;
    const uint32_t abase = sb + SM_AHI + (uint32_t)arow * 1024;
    const int arx = arow & 7;
    const int ac0 = (lane >> 4) & 1;
    const int brow = nt * 8 + (lane & 7);
    const uint32_t bbase = sb + SM_BHI + (uint32_t)brow * 1024;
    const int brx = brow & 7;
    const int bsel = (lane >> 3) & 3;

    // frag store coords (xor-swizzled parts cols, row stride 64 floats)
    const int fr0 = mt * 16 + (lane >> 2);
    const int fc  = nt * 8 + (lane & 3) * 2;
    const uint32_t fo0 = sb + SM_PARTS + (uint32_t)fr0 * 256
                       + (uint32_t)((fc ^ ((fr0 & 3) << 3)) << 2);

    float Hn8 = 0.f, Cn8 = 0.f;

    __syncthreads();

    int cur = 0;
    for (int t = 0; t < Ssz; ++t) {
        // ---- stage A hi/lo via cp.async: two k-half groups ----
        {
            const char* sh = srcH0 + (size_t)cur * hstride;
            const char* sl = srcL0 + (size_t)cur * hstride;
#pragma unroll
            for (int j = 0; j < 2; ++j) {          // k 0..255
                int chunk = cj16 + 16 * j;
                uint32_t off = (uint32_t)((chunk ^ srx) << 4);
                cp16(adst + off,         sh + chunk * 16);
                cp16(adst + 32768 + off, sl + chunk * 16);
            }
            cp_commit();
#pragma unroll
            for (int j = 2; j < 4; ++j) {          // k 256..511
                int chunk = cj16 + 16 * j;
                uint32_t off = (uint32_t)((chunk ^ srx) << 4);
                cp16(adst + off,         sh + chunk * 16);
                cp16(adst + 32768 + off, sl + chunk * 16);
            }
            cp_commit();
        }

        // prefetch x while staging flies
        float xa = __ldcg(&g_xT[t][b_off + eb]);

        // 3 independent accumulator chains (hihi / hilo / lohi)
        float cA[4] = {0.f, 0.f, 0.f, 0.f};
        float cB[4] = {0.f, 0.f, 0.f, 0.f};
        float cC[4] = {0.f, 0.f, 0.f, 0.f};

#pragma unroll
        for (int hf = 0; hf < 2; ++hf) {
            if (hf == 0) cp_wait<1>();
            else         cp_wait<0>();
            __syncthreads();
#pragma unroll 4
            for (int q = 0; q < 8; ++q) {
                int ks2 = hf * 8 + q;
                uint32_t a0h, a1h, a2h, a3h, a0l, a1l, a2l, a3l;
                uint32_t bh0, bh1, bh2, bh3, bl0, bl1, bl2, bl3;
                uint32_t boff = bbase + (uint32_t)(((ks2 * 4 + bsel) ^ brx) << 4);
                ldsm4(bh0, bh1, bh2, bh3, boff);
                ldsm4(bl0, bl1, bl2, bl3, boff + 65536);
                // even k-step
                uint32_t ao0 = abase + (uint32_t)(((ks2 * 4 + ac0) ^ arx) << 4);
                ldsm4(a0h, a1h, a2h, a3h, ao0);
                ldsm4(a0l, a1l, a2l, a3l, ao0 + 32768);
                mma16816(cA, a0h, a1h, a2h, a3h, bh0, bh1);
                mma16816(cB, a0h, a1h, a2h, a3h, bl0, bl1);
                mma16816(cC, a0l, a1l, a2l, a3l, bh0, bh1);
                // odd k-step
                uint32_t ao1 = abase + (uint32_t)(((ks2 * 4 + 2 + ac0) ^ arx) << 4);
                ldsm4(a0h, a1h, a2h, a3h, ao1);
                ldsm4(a0l, a1l, a2l, a3l, ao1 + 32768);
                mma16816(cA, a0h, a1h, a2h, a3h, bh2, bh3);
                mma16816(cB, a0h, a1h, a2h, a3h, bl2, bl3);
                mma16816(cC, a0l, a1l, a2l, a3l, bh2, bh3);
            }
        }

        // combine chains, frag -> parts (xor-swizzled)
        {
            float c0 = cA[0] + cB[0] + cC[0];
            float c1 = cA[1] + cB[1] + cC[1];
            float c2 = cA[2] + cB[2] + cC[2];
            float c3 = cA[3] + cB[3] + cC[3];
            asm volatile("st.shared.v2.f32 [%0], {%1,%2};" :: "r"(fo0), "f"(c0), "f"(c1));
            asm volatile("st.shared.v2.f32 [%0], {%1,%2};" :: "r"(fo0 + 8 * 256), "f"(c2), "f"(c3));
        }
        __syncthreads();

        // ---- distributed epilogue: thread owns (eb, ehl) ----
        {
            const int sw = (eb & 3) << 3;
            float g0 = parts[eb * 64 + ((ehl * 4 + 0) ^ sw)];
            float g1 = parts[eb * 64 + ((ehl * 4 + 1) ^ sw)];
            float g2 = parts[eb * 64 + ((ehl * 4 + 2) ^ sw)];
            float g3 = parts[eb * 64 + ((ehl * 4 + 3) ^ sw)];
            int gc = ehl * 4;
            float gi  = fmaf(xa, W0s[gc + 0], g0 + Bss[gc + 0]);
            float gf  = fmaf(xa, W0s[gc + 1], g1 + Bss[gc + 1]);
            float gch = fmaf(xa, W0s[gc + 2], g2 + Bss[gc + 2]);
            float go  = fmaf(xa, W0s[gc + 3], g3 + Bss[gc + 3]);
            float Cold = Cs[eb * 16 + ehl];
            float I  = sigmoidf_(gi);
            float F  = sigmoidf_(gf);
            float Ch = tanhf_(gch);
            float Cn = F * Cold + I * Ch;
            float Hv = go * tanhf_(Cn);        // O has no sigmoid (faithful)
            __nv_bfloat16 hi = __float2bfloat16(Hv);
            __nv_bfloat16 lo = __float2bfloat16(Hv - __bfloat162float(hi));
            g_Hhi[cur ^ 1][b_off + eb][h_off + ehl] = hi;
            g_Hlo[cur ^ 1][b_off + eb][h_off + ehl] = lo;
            Cs[eb * 16 + ehl] = Cn;
            Hn8 = Hv; Cn8 = Cn;
        }

        // sync only the 32 CTAs of this batch quarter
        quarter_barrier((unsigned)(t + 1) * 32, qctr);
        cur ^= 1;
    }

    // outputs: (H, H, C), each [B][HID]
    {
        int base = (b_off + eb) * Hsz + h_off + ehl;
        out[base]                 = Hn8;
        out[Bsz * Hsz + base]     = Hn8;
        out[2 * Bsz * Hsz + base] = Cn8;
    }
}

extern "C" void kernel_launch(void* const* d_in, const int* in_sizes, int n_in,
                              void* d_out, int out_size) {
    (void)in_sizes; (void)n_in; (void)out_size;
    const float* x  = (const float*)d_in[0];
    const float* Hp = (const float*)d_in[1];
    const float* Cp = (const float*)d_in[2];
    const float* Wi = (const float*)d_in[3];
    const float* bi = (const float*)d_in[4];
    const float* Wf = (const float*)d_in[5];
    const float* bf = (const float*)d_in[6];
    const float* Wc = (const float*)d_in[7];
    const float* bc = (const float*)d_in[8];
    const float* Wo = (const float*)d_in[9];
    const float* bo = (const float*)d_in[10];

    cudaFuncSetAttribute(lstm_kernel,
                         cudaFuncAttributeMaxDynamicSharedMemorySize, SM_TOTAL);

    lstm_init_kernel<<<(2048 * 512 + 255) / 256, 256>>>(Hp, x, Wi, Wf, Wc, Wo);
    lstm_kernel<<<NBLK, NTHR, SM_TOTAL>>>(Cp, Wi, bi, Wf, bf, Wc, bc,
                                          Wo, bo, (float*)d_out);
}